// round 3
// baseline (speedup 1.0000x reference)
#include <cuda_runtime.h>
#include <cuda_bf16.h>

#define B_  16
#define T_  64
#define V_  32000
#define E_  256
#define H_  1024
#define G4  4096
#define BH  (B_*H_)
#define NBLK 128
#define NEGV (-1e9f)

// ---------------- device scratch ----------------
__device__ float g_qemb[B_*T_*E_];
__device__ float g_remb[B_*T_*E_];
__device__ float g_hA[2*BH];       // double-buffered h
__device__ float g_attnA[2*BH];    // double-buffered attn carry
__device__ float g_c[BH];
__device__ float g_q[BH];
__device__ float g_ctx[BH];
__device__ float g_mem[B_*T_*H_];
__device__ float g_keys[B_*T_*H_];
__device__ float g_dec_out[B_*T_*H_];
__device__ float g_scores[B_*T_];
__device__ unsigned int g_bar_count = 0;
__device__ unsigned int g_bar_gen   = 0;

// ---------------- helpers ----------------
__device__ __forceinline__ float sigf(float x) {
    return 1.0f / (1.0f + __expf(-x));
}
__device__ __forceinline__ float tanh_fast(float x) {
    float ax = fabsf(x);
    float e  = __expf(2.0f * ax);
    float r  = 1.0f - 2.0f / (e + 1.0f);
    return copysignf(r, x);
}

// grid-wide barrier: all NBLK blocks resident (NBLK <= 148)
__device__ __forceinline__ void grid_barrier() {
    __syncthreads();
    if (threadIdx.x == 0) {
        __threadfence();
        unsigned int gen = *((volatile unsigned int*)&g_bar_gen);
        unsigned int old = atomicAdd(&g_bar_count, 1u);
        if (old == NBLK - 1) {
            g_bar_count = 0;
            __threadfence();
            *((volatile unsigned int*)&g_bar_gen) = gen + 1;
        } else {
            while (*((volatile unsigned int*)&g_bar_gen) == gen) {}
            __threadfence();
        }
    }
    __syncthreads();
}

__device__ __forceinline__ void fma16(float w, const float4* xr, float* acc) {
    float4 x0 = xr[0], x1 = xr[1], x2 = xr[2], x3 = xr[3];
    acc[0]+=x0.x*w; acc[1]+=x0.y*w; acc[2]+=x0.z*w; acc[3]+=x0.w*w;
    acc[4]+=x1.x*w; acc[5]+=x1.y*w; acc[6]+=x1.z*w; acc[7]+=x1.w*w;
    acc[8]+=x2.x*w; acc[9]+=x2.y*w; acc[10]+=x2.z*w; acc[11]+=x2.w*w;
    acc[12]+=x3.x*w; acc[13]+=x3.y*w; acc[14]+=x3.z*w; acc[15]+=x3.w*w;
}

// ---------------- K0: embedding gather + zero state ----------------------
__global__ void k_init(const int* __restrict__ enc_in,
                       const int* __restrict__ dec_in,
                       const float* __restrict__ emb) {
    int i = blockIdx.x * 256 + threadIdx.x;
    const int NE = B_*T_*E_;           // 262144
    if (i < NE) {
        int bt = i >> 8, e = i & 255;
        g_qemb[i] = emb[(size_t)enc_in[bt] * E_ + e];
    } else if (i < 2*NE) {
        int j = i - NE;
        int bt = j >> 8, e = j & 255;
        g_remb[j] = emb[(size_t)dec_in[bt] * E_ + e];
    } else {
        int j = i - 2*NE;
        if (j < BH)            g_hA[j] = 0.f;
        else if (j < 2*BH)     g_c[j - BH] = 0.f;
        else if (j < 3*BH)     g_attnA[j - 2*BH] = 0.f;
    }
}

// ================= persistent encoder =================
// 128 blocks x 256 threads. Block j owns gate-matched cols
// {g*1024 + j*8 + hl : g in 0..3, hl in 0..7}. One grid barrier per step.
__global__ __launch_bounds__(256) void k_encoder(const float* __restrict__ W,
                                                 const float* __restrict__ bias,
                                                 const int* __restrict__ enc_len) {
    __shared__ __align__(16) float xs[320*16];     // 20KB chunk of x
    __shared__ float red[16*8*32];                 // [b][ks][cl] 16KB
    const int j  = blockIdx.x;
    const int tt = threadIdx.x;
    const int cl = tt & 31, ks = tt >> 5;          // warp <-> kslice
    const int g  = cl >> 3, hl = cl & 7;
    const int col = g*1024 + j*8 + hl;
    const float* Wcol = W + col;

    for (int t = 0; t < T_; t++) {
        const float* hbuf = g_hA + (t & 1)*BH;
        float acc[16];
#pragma unroll
        for (int b = 0; b < 16; b++) acc[b] = 0.f;

        for (int c = 0; c < 4; c++) {              // K=1280 in 4x320 chunks
            __syncthreads();
            for (int i = tt; i < 320*16; i += 256) {
                int k = i >> 4, b = i & 15;
                int gk = c*320 + k;
                xs[i] = (gk < E_) ? g_qemb[(b*T_ + t)*E_ + gk]
                                  : hbuf[b*H_ + gk - E_];
            }
            __syncthreads();
            const float* Wp = Wcol + (size_t)(c*320 + ks*40) * G4;
            const float4* xp = (const float4*)(xs + (ks*40)*16);
#pragma unroll 4
            for (int k = 0; k < 40; k++) {
                float w = Wp[(size_t)k * G4];
                fma16(w, xp + k*4, acc);
            }
        }
        __syncthreads();
#pragma unroll
        for (int b = 0; b < 16; b++) red[b*256 + ks*32 + cl] = acc[b];
        __syncthreads();

        if (tt < 128) {
            int hh = tt & 7, b = tt >> 3;
            float zi = bias[       j*8+hh], zj = bias[1024 + j*8+hh];
            float zf = bias[2048 + j*8+hh], zo = bias[3072 + j*8+hh];
#pragma unroll
            for (int s = 0; s < 8; s++) {
                const float* r = red + b*256 + s*32;
                zi += r[hh]; zj += r[8+hh]; zf += r[16+hh]; zo += r[24+hh];
            }
            int idx = b*H_ + j*8 + hh;
            float cc = g_c[idx];
            float cn = cc * sigf(zf + 1.f) + sigf(zi)*tanh_fast(zj);
            float hn = tanh_fast(cn)*sigf(zo);
            bool valid = t < enc_len[b];
            if (valid) g_c[idx] = cn;
            float* hout = g_hA + ((t+1)&1)*BH;
            hout[idx] = valid ? hn : hbuf[idx];
            g_mem[(size_t)(b*T_ + t)*H_ + j*8 + hh] = valid ? hn : 0.f;
        }
        grid_barrier();
    }
}

// ================= persistent decoder =================
// 128 blocks x 256 threads, 5 grid barriers per step.
__global__ __launch_bounds__(256) void k_decoder(
    const float* __restrict__ Wd, const float* __restrict__ bias,
    const float* __restrict__ Wq, const float* __restrict__ v_att,
    const float* __restrict__ Wa,
    const int* __restrict__ enc_len, const int* __restrict__ dec_len) {
    __shared__ __align__(16) float xs[288*16];     // 18KB
    __shared__ float red[4096];                    // 16KB
    __shared__ float al[64];
    const int j  = blockIdx.x;
    const int tt = threadIdx.x;
    // phase A mapping
    const int clA = tt & 31, ksA = tt >> 5;
    const int gA = clA >> 3, hlA = clA & 7;
    const int colA = gA*1024 + j*8 + hlA;
    // phase B/E mapping
    const int cl8 = tt & 7, ks32 = tt >> 3;
    const int colB = j*8 + cl8;

    for (int t = 0; t < T_; t++) {
        const float* hbuf    = g_hA    + (t & 1)*BH;
        const float* attnbuf = g_attnA + (t & 1)*BH;
        float* h2buf         = g_hA    + ((t+1)&1)*BH;
        float* attn_nx       = g_attnA + ((t+1)&1)*BH;

        // ---- Phase A: z = [emb,attn,h] @ Wd  + gates -> h2,c2 ----
        {
            float acc[16];
#pragma unroll
            for (int b = 0; b < 16; b++) acc[b] = 0.f;
            for (int c = 0; c < 8; c++) {          // K=2304 in 8x288
                __syncthreads();
                for (int i = tt; i < 288*16; i += 256) {
                    int k = i >> 4, b = i & 15;
                    int gk = c*288 + k;
                    float v;
                    if (gk < 256)        v = g_remb[(b*T_ + t)*E_ + gk];
                    else if (gk < 1280)  v = attnbuf[b*H_ + gk - 256];
                    else                 v = hbuf[b*H_ + gk - 1280];
                    xs[i] = v;
                }
                __syncthreads();
                const float* Wp = Wd + (size_t)(c*288 + ksA*36) * G4 + colA;
                const float4* xp = (const float4*)(xs + (ksA*36)*16);
#pragma unroll 4
                for (int k = 0; k < 36; k++) {
                    float w = Wp[(size_t)k * G4];
                    fma16(w, xp + k*4, acc);
                }
            }
            __syncthreads();
#pragma unroll
            for (int b = 0; b < 16; b++) red[b*256 + ksA*32 + clA] = acc[b];
            __syncthreads();
            if (tt < 128) {
                int hh = tt & 7, b = tt >> 3;
                float zi = bias[       j*8+hh], zj = bias[1024 + j*8+hh];
                float zf = bias[2048 + j*8+hh], zo = bias[3072 + j*8+hh];
#pragma unroll
                for (int s = 0; s < 8; s++) {
                    const float* r = red + b*256 + s*32;
                    zi += r[hh]; zj += r[8+hh]; zf += r[16+hh]; zo += r[24+hh];
                }
                int idx = b*H_ + j*8 + hh;
                float cc = g_c[idx];
                float cn = cc * sigf(zf + 1.f) + sigf(zi)*tanh_fast(zj);
                float hn = tanh_fast(cn)*sigf(zo);
                g_c[idx]  = cn;
                h2buf[idx] = hn;
            }
        }
        grid_barrier();

        // ---- Phase B: query = h2 @ Wq (block j -> 8 cols) ----
        {
            float acc[16];
#pragma unroll
            for (int b = 0; b < 16; b++) acc[b] = 0.f;
            for (int c = 0; c < 4; c++) {          // K=1024 in 4x256
                __syncthreads();
                for (int i = tt; i < 256*16; i += 256) {
                    int k = i >> 4, b = i & 15;
                    xs[i] = h2buf[b*H_ + c*256 + k];
                }
                __syncthreads();
                const float* Wp = Wq + (size_t)(c*256 + ks32*8) * H_ + colB;
                const float4* xp = (const float4*)(xs + (ks32*8)*16);
#pragma unroll
                for (int k = 0; k < 8; k++) {
                    float w = Wp[(size_t)k * H_];
                    fma16(w, xp + k*4, acc);
                }
            }
            __syncthreads();
#pragma unroll
            for (int b = 0; b < 16; b++) red[b*256 + ks32*8 + cl8] = acc[b];
            __syncthreads();
            if (tt < 128) {
                int clq = tt & 7, b = tt >> 3;
                float q = 0.f;
#pragma unroll
                for (int s = 0; s < 32; s++) q += red[b*256 + s*8 + clq];
                g_q[b*H_ + j*8 + clq] = q;
            }
        }
        grid_barrier();

        // ---- Phase C: scores[b][t2] = v . tanh(keys + q) ----
        {
            int pair = j*8 + (tt >> 5);            // 1024 (b,t2) pairs
            int b = pair >> 6, t2 = pair & 63;
            int lane = tt & 31;
            const float* kr = g_keys + (size_t)(b*T_ + t2)*H_;
            const float* qr = g_q + b*H_;
            float s = 0.f;
            for (int h = lane; h < H_; h += 32)
                s += tanh_fast(kr[h] + qr[h]) * v_att[h];
#pragma unroll
            for (int o = 16; o > 0; o >>= 1) s += __shfl_xor_sync(0xffffffffu, s, o);
            if (lane == 0) g_scores[b*T_ + t2] = s;
        }
        grid_barrier();

        // ---- Phase D: softmax + context (block j -> b=j>>3, 128 h) ----
        {
            int b = j >> 3, h0 = (j & 7) * 128;
            if (tt < 32) {
                int L = enc_len[b];
                float s0 = (tt      < L) ? g_scores[b*T_ + tt]      : NEGV;
                float s1 = (tt + 32 < L) ? g_scores[b*T_ + tt + 32] : NEGV;
                float m = fmaxf(s0, s1);
#pragma unroll
                for (int o = 16; o > 0; o >>= 1) m = fmaxf(m, __shfl_xor_sync(0xffffffffu, m, o));
                float e0 = __expf(s0 - m), e1 = __expf(s1 - m);
                float ss = e0 + e1;
#pragma unroll
                for (int o = 16; o > 0; o >>= 1) ss += __shfl_xor_sync(0xffffffffu, ss, o);
                float inv = 1.f / ss;
                al[tt] = e0 * inv; al[tt + 32] = e1 * inv;
            }
            __syncthreads();
            if (tt < 128) {
                int h = h0 + tt;
                const float* mb = g_mem + (size_t)b*T_*H_ + h;
                float a = 0.f;
#pragma unroll
                for (int t2 = 0; t2 < T_; t2++) a += al[t2] * mb[(size_t)t2 * H_];
                g_ctx[b*H_ + h] = a;
            }
        }
        grid_barrier();

        // ---- Phase E: attn2 = [h2, ctx] @ Wa ----
        {
            float acc[16];
#pragma unroll
            for (int b = 0; b < 16; b++) acc[b] = 0.f;
            for (int c = 0; c < 8; c++) {          // K=2048 in 8x256
                __syncthreads();
                for (int i = tt; i < 256*16; i += 256) {
                    int k = i >> 4, b = i & 15;
                    int gk = c*256 + k;
                    xs[i] = (gk < 1024) ? h2buf[b*H_ + gk]
                                        : g_ctx[b*H_ + gk - 1024];
                }
                __syncthreads();
                const float* Wp = Wa + (size_t)(c*256 + ks32*8) * H_ + colB;
                const float4* xp = (const float4*)(xs + (ks32*8)*16);
#pragma unroll
                for (int k = 0; k < 8; k++) {
                    float w = Wp[(size_t)k * H_];
                    fma16(w, xp + k*4, acc);
                }
            }
            __syncthreads();
#pragma unroll
            for (int b = 0; b < 16; b++) red[b*256 + ks32*8 + cl8] = acc[b];
            __syncthreads();
            if (tt < 128) {
                int cla = tt & 7, b = tt >> 3;
                float a = 0.f;
#pragma unroll
                for (int s = 0; s < 32; s++) a += red[b*256 + s*8 + cla];
                int hh = j*8 + cla;
                attn_nx[b*H_ + hh] = a;
                g_dec_out[(size_t)(b*T_ + t)*H_ + hh] = (t < dec_len[b]) ? a : 0.f;
            }
        }
        grid_barrier();
    }
}

// ---------------- big SGEMM: 128x128 tile, BK=8, 8x8 microtile ------------
__global__ __launch_bounds__(256, 2) void sgemm128(int mode,
                                                   const float* __restrict__ Bm,
                                                   float* __restrict__ Cext,
                                                   int N) {
    const float* A = mode ? g_dec_out : g_mem;
    float* C = mode ? Cext : g_keys;
    __shared__ __align__(16) float As[2][8][132];
    __shared__ __align__(16) float Bs[2][8][128];
    const int tid = threadIdx.x;
    const int m0 = blockIdx.y * 128, n0 = blockIdx.x * 128;
    const int tx = tid & 15, ty = tid >> 4;
    const int la_r = tid >> 1, la_c = (tid & 1) * 4;
    const int lb_r = tid >> 5, lb_c = (tid & 31) * 4;

    float acc[8][8];
#pragma unroll
    for (int i = 0; i < 8; i++)
#pragma unroll
        for (int j = 0; j < 8; j++) acc[i][j] = 0.f;

    {
        float4 a4 = *(const float4*)(A  + (size_t)(m0 + la_r) * 1024 + la_c);
        float4 b4 = *(const float4*)(Bm + (size_t)lb_r * N + n0 + lb_c);
        As[0][la_c+0][la_r] = a4.x; As[0][la_c+1][la_r] = a4.y;
        As[0][la_c+2][la_r] = a4.z; As[0][la_c+3][la_r] = a4.w;
        *(float4*)&Bs[0][lb_r][lb_c] = b4;
    }
    __syncthreads();

    const int nk = 1024 / 8;
    for (int kt = 0; kt < nk; kt++) {
        const int cur = kt & 1;
        float4 a4n, b4n;
        const bool nx = (kt + 1) < nk;
        if (nx) {
            int kb = (kt + 1) * 8;
            a4n = *(const float4*)(A  + (size_t)(m0 + la_r) * 1024 + kb + la_c);
            b4n = *(const float4*)(Bm + (size_t)(kb + lb_r) * N + n0 + lb_c);
        }
#pragma unroll
        for (int k = 0; k < 8; k++) {
            const float* asr = &As[cur][k][0];
            const float* bsr = &Bs[cur][k][0];
            float4 x0 = *(const float4*)(asr + ty*4);
            float4 x1 = *(const float4*)(asr + 64 + ty*4);
            float4 y0 = *(const float4*)(bsr + tx*4);
            float4 y1 = *(const float4*)(bsr + 64 + tx*4);
            float xa[8] = {x0.x,x0.y,x0.z,x0.w,x1.x,x1.y,x1.z,x1.w};
            float yb[8] = {y0.x,y0.y,y0.z,y0.w,y1.x,y1.y,y1.z,y1.w};
#pragma unroll
            for (int i = 0; i < 8; i++)
#pragma unroll
                for (int j = 0; j < 8; j++)
                    acc[i][j] += xa[i] * yb[j];
        }
        if (nx) {
            const int nxt = cur ^ 1;
            As[nxt][la_c+0][la_r] = a4n.x; As[nxt][la_c+1][la_r] = a4n.y;
            As[nxt][la_c+2][la_r] = a4n.z; As[nxt][la_c+3][la_r] = a4n.w;
            *(float4*)&Bs[nxt][lb_r][lb_c] = b4n;
            __syncthreads();
        }
    }

#pragma unroll
    for (int i = 0; i < 8; i++) {
        int r = m0 + ((i < 4) ? (ty*4 + i) : (64 + ty*4 + (i - 4)));
        float4 v0 = make_float4(acc[i][0], acc[i][1], acc[i][2], acc[i][3]);
        float4 v1 = make_float4(acc[i][4], acc[i][5], acc[i][6], acc[i][7]);
        *(float4*)(C + (size_t)r * N + n0 + tx*4)      = v0;
        *(float4*)(C + (size_t)r * N + n0 + 64 + tx*4) = v1;
    }
}

// ------------------------------ launcher ----------------------------------
extern "C" void kernel_launch(void* const* d_in, const int* in_sizes, int n_in,
                              void* d_out, int out_size) {
    const int*   enc_in  = (const int*)  d_in[0];
    const int*   dec_in  = (const int*)  d_in[1];
    const int*   enc_len = (const int*)  d_in[2];
    const int*   dec_len = (const int*)  d_in[3];
    const float* emb     = (const float*)d_in[4];
    const float* enc_k   = (const float*)d_in[5];
    const float* enc_b   = (const float*)d_in[6];
    const float* dec_k   = (const float*)d_in[7];
    const float* dec_b   = (const float*)d_in[8];
    const float* Wm      = (const float*)d_in[9];
    const float* Wq      = (const float*)d_in[10];
    const float* v_att   = (const float*)d_in[11];
    const float* attn_k  = (const float*)d_in[12];
    const float* out_k   = (const float*)d_in[13];
    float* out = (float*)d_out;

    k_init<<<2240, 256>>>(enc_in, dec_in, emb);
    k_encoder<<<NBLK, 256>>>(enc_k, enc_b, enc_len);
    sgemm128<<<dim3(8, 8), 256>>>(0, Wm, nullptr, 1024);
    k_decoder<<<NBLK, 256>>>(dec_k, dec_b, Wq, v_att, attn_k, enc_len, dec_len);
    sgemm128<<<dim3(250, 8), 256>>>(1, out_k, out, 32000);
}

// round 5
// speedup vs baseline: 1.2075x; 1.2075x over previous
#include <cuda_runtime.h>
#include <cuda_bf16.h>

#define B_  16
#define T_  64
#define V_  32000
#define E_  256
#define H_  1024
#define G4  4096
#define BH  (B_*H_)
#define NBLK 128
#define NEGV (-1e9f)

// ---------------- device scratch ----------------
__device__ float g_qemb[B_*T_*E_];
__device__ float g_remb[B_*T_*E_];
__device__ float g_hA[2*BH];       // double-buffered h
__device__ float g_attnA[2*BH];    // double-buffered attn carry
__device__ float g_c[BH];
__device__ float g_q[BH];
__device__ float g_ctx[BH];
__device__ float g_mem[B_*T_*H_];
__device__ float g_keys[B_*T_*H_];
__device__ float g_dec_out[B_*T_*H_];
__device__ float g_scores[B_*T_];
// barrier state: arrive slots and release flag on separate padded lines
__device__ __align__(128) volatile unsigned g_arrive[NBLK];
__device__ __align__(128) volatile unsigned g_release;

// ---------------- helpers ----------------
__device__ __forceinline__ float sigf(float x) {
    return 1.0f / (1.0f + __expf(-x));
}
__device__ __forceinline__ float tanh_fast(float x) {
    float ax = fabsf(x);
    float e  = __expf(2.0f * ax);
    float r  = 1.0f - 2.0f / (e + 1.0f);
    return copysignf(r, x);
}

// fast grid barrier: distributed STG arrivals + block-0 parallel aggregation.
// ep is a unique compile-time-ish epoch per call site (equality match -> safe
// across kernel boundaries and graph replays; k_init resets state anyway).
__device__ __forceinline__ void grid_barrier(int j, int tt, unsigned ep) {
    __syncthreads();
    if (j == 0) {
        if (tt < NBLK) {
            if (tt == 0) { __threadfence(); g_arrive[0] = ep; }
            while (g_arrive[tt] != ep) {}
        }
        __syncthreads();
        if (tt == 0) { __threadfence(); g_release = ep; }
    } else {
        if (tt == 0) {
            __threadfence();
            g_arrive[j] = ep;
            while (g_release != ep) {}
            __threadfence();
        }
    }
    __syncthreads();
}

__device__ __forceinline__ void fma16(float w, const float4* xr, float* acc) {
    float4 x0 = xr[0], x1 = xr[1], x2 = xr[2], x3 = xr[3];
    acc[0]+=x0.x*w; acc[1]+=x0.y*w; acc[2]+=x0.z*w; acc[3]+=x0.w*w;
    acc[4]+=x1.x*w; acc[5]+=x1.y*w; acc[6]+=x1.z*w; acc[7]+=x1.w*w;
    acc[8]+=x2.x*w; acc[9]+=x2.y*w; acc[10]+=x2.z*w; acc[11]+=x2.w*w;
    acc[12]+=x3.x*w; acc[13]+=x3.y*w; acc[14]+=x3.z*w; acc[15]+=x3.w*w;
}

// ---------------- K0: embedding gather + zero state + barrier reset -------
__global__ void k_init(const int* __restrict__ enc_in,
                       const int* __restrict__ dec_in,
                       const float* __restrict__ emb) {
    if (blockIdx.x == 0) {
        if (threadIdx.x < NBLK) g_arrive[threadIdx.x] = 0;
        if (threadIdx.x == NBLK) g_release = 0;
    }
    int i = blockIdx.x * 256 + threadIdx.x;
    const int NE = B_*T_*E_;           // 262144
    if (i < NE) {
        int bt = i >> 8, e = i & 255;
        g_qemb[i] = emb[(size_t)enc_in[bt] * E_ + e];
    } else if (i < 2*NE) {
        int j = i - NE;
        int bt = j >> 8, e = j & 255;
        g_remb[j] = emb[(size_t)dec_in[bt] * E_ + e];
    } else {
        int j = i - 2*NE;
        if (j < BH)            g_hA[j] = 0.f;
        else if (j < 2*BH)     g_c[j - BH] = 0.f;
        else if (j < 3*BH)     g_attnA[j - 2*BH] = 0.f;
    }
}

// ================= persistent encoder =================
// 128 blocks x 256 threads. Block j owns gate-matched cols
// {g*1024 + j*8 + hl}. One grid barrier per step. epochs 1..64.
__global__ __launch_bounds__(256) void k_encoder(const float* __restrict__ W,
                                                 const float* __restrict__ bias,
                                                 const int* __restrict__ enc_len) {
    __shared__ __align__(16) float xs[320*16];
    __shared__ float red[16*8*32];
    const int j  = blockIdx.x;
    const int tt = threadIdx.x;
    const int cl = tt & 31, ks = tt >> 5;
    const int g  = cl >> 3, hl = cl & 7;
    const int col = g*1024 + j*8 + hl;
    const float* Wcol = W + col;

    for (int t = 0; t < T_; t++) {
        const float* hbuf = g_hA + (t & 1)*BH;
        float acc[16];
#pragma unroll
        for (int b = 0; b < 16; b++) acc[b] = 0.f;

        for (int c = 0; c < 4; c++) {              // K=1280 in 4x320
            __syncthreads();
#pragma unroll
            for (int r = 0; r < 20; r++) {         // 320*16/256
                int i = tt + r*256;
                int k = i >> 4, b = i & 15;
                int gk = c*320 + k;
                xs[i] = (gk < E_) ? g_qemb[(b*T_ + t)*E_ + gk]
                                  : hbuf[b*H_ + gk - E_];
            }
            __syncthreads();
            const float* Wp = Wcol + (size_t)(c*320 + ks*40) * G4;
            const float4* xp = (const float4*)(xs + (ks*40)*16);
#pragma unroll
            for (int kb = 0; kb < 5; kb++) {       // 40 iters, MLP=8
                float w[8];
#pragma unroll
                for (int u = 0; u < 8; u++) w[u] = Wp[(size_t)(kb*8+u) * G4];
#pragma unroll
                for (int u = 0; u < 8; u++) fma16(w[u], xp + (kb*8+u)*4, acc);
            }
        }
        __syncthreads();
#pragma unroll
        for (int b = 0; b < 16; b++) red[b*256 + ks*32 + cl] = acc[b];
        __syncthreads();

        if (tt < 128) {
            int hh = tt & 7, b = tt >> 3;
            float zi = bias[       j*8+hh], zj = bias[1024 + j*8+hh];
            float zf = bias[2048 + j*8+hh], zo = bias[3072 + j*8+hh];
#pragma unroll
            for (int s = 0; s < 8; s++) {
                const float* r = red + b*256 + s*32;
                zi += r[hh]; zj += r[8+hh]; zf += r[16+hh]; zo += r[24+hh];
            }
            int idx = b*H_ + j*8 + hh;
            float cc = g_c[idx];
            float cn = cc * sigf(zf + 1.f) + sigf(zi)*tanh_fast(zj);
            float hn = tanh_fast(cn)*sigf(zo);
            bool valid = t < enc_len[b];
            if (valid) g_c[idx] = cn;
            float* hout = g_hA + ((t+1)&1)*BH;
            hout[idx] = valid ? hn : hbuf[idx];
            g_mem[(size_t)(b*T_ + t)*H_ + j*8 + hh] = valid ? hn : 0.f;
        }
        grid_barrier(j, tt, (unsigned)(t + 1));
    }
}

// ================= persistent decoder =================
// 128 blocks x 256 threads, 5 grid barriers per step. epochs 65..384.
__global__ __launch_bounds__(256) void k_decoder(
    const float* __restrict__ Wd, const float* __restrict__ bias,
    const float* __restrict__ Wq, const float* __restrict__ v_att,
    const float* __restrict__ Wa,
    const int* __restrict__ enc_len, const int* __restrict__ dec_len) {
    __shared__ __align__(16) float xs[288*16];
    __shared__ float red[4096];
    __shared__ float al[64];
    const int j  = blockIdx.x;
    const int tt = threadIdx.x;
    const int clA = tt & 31, ksA = tt >> 5;
    const int gA = clA >> 3, hlA = clA & 7;
    const int colA = gA*1024 + j*8 + hlA;
    const int cl8 = tt & 7, ks32 = tt >> 3;
    const int colB = j*8 + cl8;

    for (int t = 0; t < T_; t++) {
        const unsigned ep0 = 64u + 5u*(unsigned)t;
        const float* hbuf    = g_hA    + (t & 1)*BH;
        const float* attnbuf = g_attnA + (t & 1)*BH;
        float* h2buf         = g_hA    + ((t+1)&1)*BH;
        float* attn_nx       = g_attnA + ((t+1)&1)*BH;

        // ---- Phase A: z = [emb,attn,h] @ Wd + gates -> h2,c2 ----
        {
            float acc[16];
#pragma unroll
            for (int b = 0; b < 16; b++) acc[b] = 0.f;
            for (int c = 0; c < 8; c++) {          // K=2304 in 8x288
                __syncthreads();
#pragma unroll
                for (int r = 0; r < 18; r++) {     // 288*16/256
                    int i = tt + r*256;
                    int k = i >> 4, b = i & 15;
                    int gk = c*288 + k;
                    float v;
                    if (gk < 256)        v = g_remb[(b*T_ + t)*E_ + gk];
                    else if (gk < 1280)  v = attnbuf[b*H_ + gk - 256];
                    else                 v = hbuf[b*H_ + gk - 1280];
                    xs[i] = v;
                }
                __syncthreads();
                const float* Wp = Wd + (size_t)(c*288 + ksA*36) * G4 + colA;
                const float4* xp = (const float4*)(xs + (ksA*36)*16);
#pragma unroll
                for (int kb = 0; kb < 3; kb++) {   // 36 iters, MLP=12
                    float w[12];
#pragma unroll
                    for (int u = 0; u < 12; u++) w[u] = Wp[(size_t)(kb*12+u) * G4];
#pragma unroll
                    for (int u = 0; u < 12; u++) fma16(w[u], xp + (kb*12+u)*4, acc);
                }
            }
            __syncthreads();
#pragma unroll
            for (int b = 0; b < 16; b++) red[b*256 + ksA*32 + clA] = acc[b];
            __syncthreads();
            if (tt < 128) {
                int hh = tt & 7, b = tt >> 3;
                float zi = bias[       j*8+hh], zj = bias[1024 + j*8+hh];
                float zf = bias[2048 + j*8+hh], zo = bias[3072 + j*8+hh];
#pragma unroll
                for (int s = 0; s < 8; s++) {
                    const float* r = red + b*256 + s*32;
                    zi += r[hh]; zj += r[8+hh]; zf += r[16+hh]; zo += r[24+hh];
                }
                int idx = b*H_ + j*8 + hh;
                float cc = g_c[idx];
                float cn = cc * sigf(zf + 1.f) + sigf(zi)*tanh_fast(zj);
                float hn = tanh_fast(cn)*sigf(zo);
                g_c[idx]  = cn;
                h2buf[idx] = hn;
            }
        }
        grid_barrier(j, tt, ep0 + 1);

        // ---- Phase B: query = h2 @ Wq ----
        {
            float acc[16];
#pragma unroll
            for (int b = 0; b < 16; b++) acc[b] = 0.f;
            for (int c = 0; c < 4; c++) {          // K=1024 in 4x256
                __syncthreads();
#pragma unroll
                for (int r = 0; r < 16; r++) {
                    int i = tt + r*256;
                    int k = i >> 4, b = i & 15;
                    xs[i] = h2buf[b*H_ + c*256 + k];
                }
                __syncthreads();
                const float* Wp = Wq + (size_t)(c*256 + ks32*8) * H_ + colB;
                const float4* xp = (const float4*)(xs + (ks32*8)*16);
                float w[8];
#pragma unroll
                for (int u = 0; u < 8; u++) w[u] = Wp[(size_t)u * H_];
#pragma unroll
                for (int u = 0; u < 8; u++) fma16(w[u], xp + u*4, acc);
            }
            __syncthreads();
#pragma unroll
            for (int b = 0; b < 16; b++) red[b*256 + ks32*8 + cl8] = acc[b];
            __syncthreads();
            if (tt < 128) {
                int clq = tt & 7, b = tt >> 3;
                float q = 0.f;
#pragma unroll
                for (int s = 0; s < 32; s++) q += red[b*256 + s*8 + clq];
                g_q[b*H_ + j*8 + clq] = q;
            }
        }
        grid_barrier(j, tt, ep0 + 2);

        // ---- Phase C: scores[b][t2] = v . tanh(keys + q) ----
        {
            int pair = j*8 + (tt >> 5);
            int b = pair >> 6, t2 = pair & 63;
            int lane = tt & 31;
            const float* kr = g_keys + (size_t)(b*T_ + t2)*H_;
            const float* qr = g_q + b*H_;
            float s = 0.f;
#pragma unroll 8
            for (int h = lane; h < H_; h += 32)
                s += tanh_fast(kr[h] + qr[h]) * v_att[h];
#pragma unroll
            for (int o = 16; o > 0; o >>= 1) s += __shfl_xor_sync(0xffffffffu, s, o);
            if (lane == 0) g_scores[b*T_ + t2] = s;
        }
        grid_barrier(j, tt, ep0 + 3);

        // ---- Phase D: softmax + context ----
        {
            int b = j >> 3, h0 = (j & 7) * 128;
            if (tt < 32) {
                int L = enc_len[b];
                float s0 = (tt      < L) ? g_scores[b*T_ + tt]      : NEGV;
                float s1 = (tt + 32 < L) ? g_scores[b*T_ + tt + 32] : NEGV;
                float m = fmaxf(s0, s1);
#pragma unroll
                for (int o = 16; o > 0; o >>= 1) m = fmaxf(m, __shfl_xor_sync(0xffffffffu, m, o));
                float e0 = __expf(s0 - m), e1 = __expf(s1 - m);
                float ss = e0 + e1;
#pragma unroll
                for (int o = 16; o > 0; o >>= 1) ss += __shfl_xor_sync(0xffffffffu, ss, o);
                float inv = 1.f / ss;
                al[tt] = e0 * inv; al[tt + 32] = e1 * inv;
            }
            __syncthreads();
            if (tt < 128) {
                int h = h0 + tt;
                const float* mb = g_mem + (size_t)b*T_*H_ + h;
                float a = 0.f;
#pragma unroll
                for (int t2 = 0; t2 < T_; t2++) a += al[t2] * mb[(size_t)t2 * H_];
                g_ctx[b*H_ + h] = a;
            }
        }
        grid_barrier(j, tt, ep0 + 4);

        // ---- Phase E: attn2 = [h2, ctx] @ Wa ----
        {
            float acc[16];
#pragma unroll
            for (int b = 0; b < 16; b++) acc[b] = 0.f;
            for (int c = 0; c < 8; c++) {          // K=2048 in 8x256
                __syncthreads();
#pragma unroll
                for (int r = 0; r < 16; r++) {
                    int i = tt + r*256;
                    int k = i >> 4, b = i & 15;
                    int gk = c*256 + k;
                    xs[i] = (gk < 1024) ? h2buf[b*H_ + gk]
                                        : g_ctx[b*H_ + gk - 1024];
                }
                __syncthreads();
                const float* Wp = Wa + (size_t)(c*256 + ks32*8) * H_ + colB;
                const float4* xp = (const float4*)(xs + (ks32*8)*16);
                float w[8];
#pragma unroll
                for (int u = 0; u < 8; u++) w[u] = Wp[(size_t)u * H_];
#pragma unroll
                for (int u = 0; u < 8; u++) fma16(w[u], xp + u*4, acc);
            }
            __syncthreads();
#pragma unroll
            for (int b = 0; b < 16; b++) red[b*256 + ks32*8 + cl8] = acc[b];
            __syncthreads();
            if (tt < 128) {
                int cla = tt & 7, b = tt >> 3;
                float a = 0.f;
#pragma unroll
                for (int s = 0; s < 32; s++) a += red[b*256 + s*8 + cla];
                int hh = j*8 + cla;
                attn_nx[b*H_ + hh] = a;
                g_dec_out[(size_t)(b*T_ + t)*H_ + hh] = (t < dec_len[b]) ? a : 0.f;
            }
        }
        grid_barrier(j, tt, ep0 + 5);
    }
}

// ---------------- big SGEMM: 128x128 tile, BK=8, 8x8 microtile ------------
__global__ __launch_bounds__(256, 2) void sgemm128(int mode,
                                                   const float* __restrict__ Bm,
                                                   float* __restrict__ Cext,
                                                   int N) {
    const float* A = mode ? g_dec_out : g_mem;
    float* C = mode ? Cext : g_keys;
    __shared__ __align__(16) float As[2][8][132];
    __shared__ __align__(16) float Bs[2][8][128];
    const int tid = threadIdx.x;
    const int m0 = blockIdx.y * 128, n0 = blockIdx.x * 128;
    const int tx = tid & 15, ty = tid >> 4;
    const int la_r = tid >> 1, la_c = (tid & 1) * 4;
    const int lb_r = tid >> 5, lb_c = (tid & 31) * 4;

    float acc[8][8];
#pragma unroll
    for (int i = 0; i < 8; i++)
#pragma unroll
        for (int j = 0; j < 8; j++) acc[i][j] = 0.f;

    {
        float4 a4 = *(const float4*)(A  + (size_t)(m0 + la_r) * 1024 + la_c);
        float4 b4 = *(const float4*)(Bm + (size_t)lb_r * N + n0 + lb_c);
        As[0][la_c+0][la_r] = a4.x; As[0][la_c+1][la_r] = a4.y;
        As[0][la_c+2][la_r] = a4.z; As[0][la_c+3][la_r] = a4.w;
        *(float4*)&Bs[0][lb_r][lb_c] = b4;
    }
    __syncthreads();

    const int nk = 1024 / 8;
    for (int kt = 0; kt < nk; kt++) {
        const int cur = kt & 1;
        float4 a4n, b4n;
        const bool nx = (kt + 1) < nk;
        if (nx) {
            int kb = (kt + 1) * 8;
            a4n = *(const float4*)(A  + (size_t)(m0 + la_r) * 1024 + kb + la_c);
            b4n = *(const float4*)(Bm + (size_t)(kb + lb_r) * N + n0 + lb_c);
        }
#pragma unroll
        for (int k = 0; k < 8; k++) {
            const float* asr = &As[cur][k][0];
            const float* bsr = &Bs[cur][k][0];
            float4 x0 = *(const float4*)(asr + ty*4);
            float4 x1 = *(const float4*)(asr + 64 + ty*4);
            float4 y0 = *(const float4*)(bsr + tx*4);
            float4 y1 = *(const float4*)(bsr + 64 + tx*4);
            float xa[8] = {x0.x,x0.y,x0.z,x0.w,x1.x,x1.y,x1.z,x1.w};
            float yb[8] = {y0.x,y0.y,y0.z,y0.w,y1.x,y1.y,y1.z,y1.w};
#pragma unroll
            for (int i = 0; i < 8; i++)
#pragma unroll
                for (int j = 0; j < 8; j++)
                    acc[i][j] += xa[i] * yb[j];
        }
        if (nx) {
            const int nxt = cur ^ 1;
            As[nxt][la_c+0][la_r] = a4n.x; As[nxt][la_c+1][la_r] = a4n.y;
            As[nxt][la_c+2][la_r] = a4n.z; As[nxt][la_c+3][la_r] = a4n.w;
            *(float4*)&Bs[nxt][lb_r][lb_c] = b4n;
            __syncthreads();
        }
    }

#pragma unroll
    for (int i = 0; i < 8; i++) {
        int r = m0 + ((i < 4) ? (ty*4 + i) : (64 + ty*4 + (i - 4)));
        float4 v0 = make_float4(acc[i][0], acc[i][1], acc[i][2], acc[i][3]);
        float4 v1 = make_float4(acc[i][4], acc[i][5], acc[i][6], acc[i][7]);
        *(float4*)(C + (size_t)r * N + n0 + tx*4)      = v0;
        *(float4*)(C + (size_t)r * N + n0 + 64 + tx*4) = v1;
    }
}

// ------------------------------ launcher ----------------------------------
extern "C" void kernel_launch(void* const* d_in, const int* in_sizes, int n_in,
                              void* d_out, int out_size) {
    const int*   enc_in  = (const int*)  d_in[0];
    const int*   dec_in  = (const int*)  d_in[1];
    const int*   enc_len = (const int*)  d_in[2];
    const int*   dec_len = (const int*)  d_in[3];
    const float* emb     = (const float*)d_in[4];
    const float* enc_k   = (const float*)d_in[5];
    const float* enc_b   = (const float*)d_in[6];
    const float* dec_k   = (const float*)d_in[7];
    const float* dec_b   = (const float*)d_in[8];
    const float* Wm      = (const float*)d_in[9];
    const float* Wq      = (const float*)d_in[10];
    const float* v_att   = (const float*)d_in[11];
    const float* attn_k  = (const float*)d_in[12];
    const float* out_k   = (const float*)d_in[13];
    float* out = (float*)d_out;

    k_init<<<2240, 256>>>(enc_in, dec_in, emb);
    k_encoder<<<NBLK, 256>>>(enc_k, enc_b, enc_len);
    sgemm128<<<dim3(8, 8), 256>>>(0, Wm, nullptr, 1024);
    k_decoder<<<NBLK, 256>>>(dec_k, dec_b, Wq, v_att, attn_k, enc_len, dec_len);
    sgemm128<<<dim3(250, 8), 256>>>(1, out_k, out, 32000);
}

// round 7
// speedup vs baseline: 1.5566x; 1.2891x over previous
#include <cuda_runtime.h>
#include <cuda_bf16.h>

#define B_  16
#define T_  64
#define V_  32000
#define E_  256
#define H_  1024
#define G4  4096
#define BH  (B_*H_)
#define NEGV (-1e9f)

// ---------------- device scratch ----------------
__device__ float g_qemb[B_*T_*E_];
__device__ float g_remb[B_*T_*E_];
__device__ float g_zpre_enc[B_*T_*G4];   // 16MB: qemb @ Wx_enc
__device__ float g_zpre_dec[B_*T_*G4];   // 16MB: remb @ Wx_dec
__device__ float g_hA[2*BH];             // double-buffered h
__device__ float g_attnA[2*BH];          // double-buffered attn carry
__device__ float g_c[BH];
__device__ float g_q[BH];
__device__ float g_ctx[BH];
__device__ float g_mem[B_*T_*H_];
__device__ float g_keys[B_*T_*H_];
__device__ float g_dec_out[B_*T_*H_];
__device__ float g_scores[B_*T_];

// ---------------- helpers ----------------
__device__ __forceinline__ float sigf(float x) {
    return 1.0f / (1.0f + __expf(-x));
}
__device__ __forceinline__ float tanh_fast(float x) {
    float ax = fabsf(x);
    float e  = __expf(2.0f * ax);
    float r  = 1.0f - 2.0f / (e + 1.0f);
    return copysignf(r, x);
}
__device__ __forceinline__ void fma16(float w, const float4* xr, float* acc) {
    float4 x0 = xr[0], x1 = xr[1], x2 = xr[2], x3 = xr[3];
    acc[0]+=x0.x*w; acc[1]+=x0.y*w; acc[2]+=x0.z*w; acc[3]+=x0.w*w;
    acc[4]+=x1.x*w; acc[5]+=x1.y*w; acc[6]+=x1.z*w; acc[7]+=x1.w*w;
    acc[8]+=x2.x*w; acc[9]+=x2.y*w; acc[10]+=x2.z*w; acc[11]+=x2.w*w;
    acc[12]+=x3.x*w; acc[13]+=x3.y*w; acc[14]+=x3.z*w; acc[15]+=x3.w*w;
}

// ---------------- K0: embedding gather + zero state -----------------------
// grid 2368 x 256 covers 2*B*T*E embeds + 5*BH zeros
__global__ void k_init(const int* __restrict__ enc_in,
                       const int* __restrict__ dec_in,
                       const float* __restrict__ emb) {
    int i = blockIdx.x * 256 + threadIdx.x;
    const int NE = B_*T_*E_;           // 262144
    if (i < NE) {
        int bt = i >> 8, e = i & 255;
        g_qemb[i] = emb[(size_t)enc_in[bt] * E_ + e];
    } else if (i < 2*NE) {
        int j = i - NE;
        int bt = j >> 8, e = j & 255;
        g_remb[j] = emb[(size_t)dec_in[bt] * E_ + e];
    } else {
        int j = i - 2*NE;
        if (j < 2*BH)            g_hA[j] = 0.f;
        else if (j < 3*BH)       g_c[j - 2*BH] = 0.f;
        else if (j < 5*BH)       g_attnA[j - 3*BH] = 0.f;
    }
}

// ========== encoder step: h@Wh + zpre + bias -> gates (1 kernel) ==========
// 128 blocks x 256 threads. Block j owns gate-matched cols {g*1024+j*8+hl}.
__global__ __launch_bounds__(256) void k_enc_step(const float* __restrict__ W,
                                                  const float* __restrict__ bias,
                                                  const int* __restrict__ enc_len,
                                                  int t) {
    __shared__ __align__(16) float xs[256*16];
    __shared__ float red[4096];
    const int j  = blockIdx.x;
    const int tt = threadIdx.x;
    const int cl = tt & 31, ks = tt >> 5;
    const int g  = cl >> 3, hl = cl & 7;
    const int col = g*1024 + j*8 + hl;
    const float* hbuf = g_hA + (t & 1)*BH;

    float acc[16];
#pragma unroll
    for (int b = 0; b < 16; b++) acc[b] = 0.f;

#pragma unroll
    for (int c = 0; c < 4; c++) {                  // K=1024 in 4x256
        __syncthreads();
        const float* src = hbuf + c*256;
#pragma unroll
        for (int r = 0; r < 16; r++) {
            int i = tt + r*256;
            int k = i >> 4, b = i & 15;
            xs[i] = src[b*H_ + k];
        }
        __syncthreads();
        const float* Wp = W + (size_t)(E_ + c*256 + ks*32) * G4 + col;
        const float4* xp = (const float4*)(xs + (ks*32)*16);
#pragma unroll
        for (int kb = 0; kb < 4; kb++) {           // 32 k, MLP=8
            float w[8];
#pragma unroll
            for (int u = 0; u < 8; u++) w[u] = Wp[(size_t)(kb*8+u) * G4];
#pragma unroll
            for (int u = 0; u < 8; u++) fma16(w[u], xp + (kb*8+u)*4, acc);
        }
    }
    __syncthreads();
#pragma unroll
    for (int b = 0; b < 16; b++) red[b*256 + ks*32 + cl] = acc[b];
    __syncthreads();

    if (tt < 128) {
        int hh = tt & 7, b = tt >> 3;
        int c0 = j*8 + hh;
        const float* zp = g_zpre_enc + (size_t)(b*T_ + t)*G4;
        float zi = zp[c0]        + bias[c0];
        float zj = zp[1024 + c0] + bias[1024 + c0];
        float zf = zp[2048 + c0] + bias[2048 + c0];
        float zo = zp[3072 + c0] + bias[3072 + c0];
#pragma unroll
        for (int s = 0; s < 8; s++) {
            const float* r = red + b*256 + s*32;
            zi += r[hh]; zj += r[8+hh]; zf += r[16+hh]; zo += r[24+hh];
        }
        int idx = b*H_ + c0;
        float cc = g_c[idx];
        float cn = cc * sigf(zf + 1.f) + sigf(zi)*tanh_fast(zj);
        float hn = tanh_fast(cn)*sigf(zo);
        bool valid = t < enc_len[b];
        if (valid) g_c[idx] = cn;
        float* hout = g_hA + ((t+1)&1)*BH;
        hout[idx] = valid ? hn : hbuf[idx];
        g_mem[(size_t)(b*T_ + t)*H_ + c0] = valid ? hn : 0.f;
    }
}

// ========== decoder step A: [attn,h]@Wd + zpre + bias -> gates ============
__global__ __launch_bounds__(256) void k_dec_stepA(const float* __restrict__ W,
                                                   const float* __restrict__ bias,
                                                   int t) {
    __shared__ __align__(16) float xs[256*16];
    __shared__ float red[4096];
    const int j  = blockIdx.x;
    const int tt = threadIdx.x;
    const int cl = tt & 31, ks = tt >> 5;
    const int g  = cl >> 3, hl = cl & 7;
    const int col = g*1024 + j*8 + hl;
    const float* hbuf    = g_hA    + (t & 1)*BH;
    const float* attnbuf = g_attnA + (t & 1)*BH;

    float acc[16];
#pragma unroll
    for (int b = 0; b < 16; b++) acc[b] = 0.f;

#pragma unroll
    for (int c = 0; c < 8; c++) {                  // K=2048 in 8x256
        __syncthreads();
        const float* src = (c < 4) ? (attnbuf + c*256) : (hbuf + (c-4)*256);
#pragma unroll
        for (int r = 0; r < 16; r++) {
            int i = tt + r*256;
            int k = i >> 4, b = i & 15;
            xs[i] = src[b*H_ + k];
        }
        __syncthreads();
        const float* Wp = W + (size_t)(E_ + c*256 + ks*32) * G4 + col;
        const float4* xp = (const float4*)(xs + (ks*32)*16);
#pragma unroll
        for (int kb = 0; kb < 4; kb++) {
            float w[8];
#pragma unroll
            for (int u = 0; u < 8; u++) w[u] = Wp[(size_t)(kb*8+u) * G4];
#pragma unroll
            for (int u = 0; u < 8; u++) fma16(w[u], xp + (kb*8+u)*4, acc);
        }
    }
    __syncthreads();
#pragma unroll
    for (int b = 0; b < 16; b++) red[b*256 + ks*32 + cl] = acc[b];
    __syncthreads();

    if (tt < 128) {
        int hh = tt & 7, b = tt >> 3;
        int c0 = j*8 + hh;
        const float* zp = g_zpre_dec + (size_t)(b*T_ + t)*G4;
        float zi = zp[c0]        + bias[c0];
        float zj = zp[1024 + c0] + bias[1024 + c0];
        float zf = zp[2048 + c0] + bias[2048 + c0];
        float zo = zp[3072 + c0] + bias[3072 + c0];
#pragma unroll
        for (int s = 0; s < 8; s++) {
            const float* r = red + b*256 + s*32;
            zi += r[hh]; zj += r[8+hh]; zf += r[16+hh]; zo += r[24+hh];
        }
        int idx = b*H_ + c0;
        float cc = g_c[idx];
        float cn = cc * sigf(zf + 1.f) + sigf(zi)*tanh_fast(zj);
        float hn = tanh_fast(cn)*sigf(zo);
        g_c[idx] = cn;
        g_hA[((t+1)&1)*BH + idx] = hn;             // h2
    }
}

// ========== decoder: query = h2 @ Wq ======================================
__global__ __launch_bounds__(256) void k_query(const float* __restrict__ Wq, int t) {
    __shared__ __align__(16) float xs[256*16];
    __shared__ float red[4096];
    const int j  = blockIdx.x;
    const int tt = threadIdx.x;
    const int cl8 = tt & 7, ks32 = tt >> 3;
    const int colB = j*8 + cl8;
    const float* h2buf = g_hA + ((t+1)&1)*BH;

    float acc[16];
#pragma unroll
    for (int b = 0; b < 16; b++) acc[b] = 0.f;
#pragma unroll
    for (int c = 0; c < 4; c++) {                  // K=1024 in 4x256
        __syncthreads();
        const float* src = h2buf + c*256;
#pragma unroll
        for (int r = 0; r < 16; r++) {
            int i = tt + r*256;
            int k = i >> 4, b = i & 15;
            xs[i] = src[b*H_ + k];
        }
        __syncthreads();
        const float* Wp = Wq + (size_t)(c*256 + ks32*8) * H_ + colB;
        const float4* xp = (const float4*)(xs + (ks32*8)*16);
        float w[8];
#pragma unroll
        for (int u = 0; u < 8; u++) w[u] = Wp[(size_t)u * H_];
#pragma unroll
        for (int u = 0; u < 8; u++) fma16(w[u], xp + u*4, acc);
    }
    __syncthreads();
#pragma unroll
    for (int b = 0; b < 16; b++) red[b*256 + ks32*8 + cl8] = acc[b];
    __syncthreads();
    if (tt < 128) {
        int clq = tt & 7, b = tt >> 3;
        float q = 0.f;
#pragma unroll
        for (int s = 0; s < 32; s++) q += red[b*256 + s*8 + clq];
        g_q[b*H_ + j*8 + clq] = q;
    }
}

// ========== decoder: scores[b][t2] = v . tanh(keys + q) ===================
__global__ __launch_bounds__(256) void k_scores(const float* __restrict__ v_att) {
    const int j  = blockIdx.x;
    const int tt = threadIdx.x;
    int pair = j*8 + (tt >> 5);                    // 1024 (b,t2) pairs
    int b = pair >> 6, t2 = pair & 63;
    int lane = tt & 31;
    const float* kr = g_keys + (size_t)(b*T_ + t2)*H_;
    const float* qr = g_q + b*H_;
    float s = 0.f;
#pragma unroll 8
    for (int h = lane; h < H_; h += 32)
        s += tanh_fast(kr[h] + qr[h]) * v_att[h];
#pragma unroll
    for (int o = 16; o > 0; o >>= 1) s += __shfl_xor_sync(0xffffffffu, s, o);
    if (lane == 0) g_scores[b*T_ + t2] = s;
}

// ========== decoder: softmax + context ====================================
// 128 blocks x 128 threads: block j -> b=j>>3, h-range (j&7)*128..
__global__ __launch_bounds__(128) void k_ctx(const int* __restrict__ enc_len) {
    const int j  = blockIdx.x;
    const int tt = threadIdx.x;
    __shared__ float al[64];
    int b = j >> 3, h0 = (j & 7) * 128;
    if (tt < 32) {
        int L = enc_len[b];
        float s0 = (tt      < L) ? g_scores[b*T_ + tt]      : NEGV;
        float s1 = (tt + 32 < L) ? g_scores[b*T_ + tt + 32] : NEGV;
        float m = fmaxf(s0, s1);
#pragma unroll
        for (int o = 16; o > 0; o >>= 1) m = fmaxf(m, __shfl_xor_sync(0xffffffffu, m, o));
        float e0 = __expf(s0 - m), e1 = __expf(s1 - m);
        float ss = e0 + e1;
#pragma unroll
        for (int o = 16; o > 0; o >>= 1) ss += __shfl_xor_sync(0xffffffffu, ss, o);
        float inv = 1.f / ss;
        al[tt] = e0 * inv; al[tt + 32] = e1 * inv;
    }
    __syncthreads();
    int h = h0 + tt;
    const float* mb = g_mem + (size_t)b*T_*H_ + h;
    float a = 0.f;
#pragma unroll
    for (int t2 = 0; t2 < T_; t2++) a += al[t2] * mb[(size_t)t2 * H_];
    g_ctx[b*H_ + h] = a;
}

// ========== decoder: attn2 = [h2, ctx] @ Wa + finish ======================
__global__ __launch_bounds__(256) void k_attn2fin(const float* __restrict__ Wa,
                                                  const int* __restrict__ dec_len,
                                                  int t) {
    __shared__ __align__(16) float xs[256*16];
    __shared__ float red[4096];
    const int j  = blockIdx.x;
    const int tt = threadIdx.x;
    const int cl8 = tt & 7, ks32 = tt >> 3;
    const int colB = j*8 + cl8;
    const float* h2buf = g_hA + ((t+1)&1)*BH;

    float acc[16];
#pragma unroll
    for (int b = 0; b < 16; b++) acc[b] = 0.f;
#pragma unroll
    for (int c = 0; c < 8; c++) {                  // K=2048 in 8x256
        __syncthreads();
        const float* src = (c < 4) ? (h2buf + c*256) : (g_ctx + (c-4)*256);
#pragma unroll
        for (int r = 0; r < 16; r++) {
            int i = tt + r*256;
            int k = i >> 4, b = i & 15;
            xs[i] = src[b*H_ + k];
        }
        __syncthreads();
        const float* Wp = Wa + (size_t)(c*256 + ks32*8) * H_ + colB;
        const float4* xp = (const float4*)(xs + (ks32*8)*16);
        float w[8];
#pragma unroll
        for (int u = 0; u < 8; u++) w[u] = Wp[(size_t)u * H_];
#pragma unroll
        for (int u = 0; u < 8; u++) fma16(w[u], xp + u*4, acc);
    }
    __syncthreads();
#pragma unroll
    for (int b = 0; b < 16; b++) red[b*256 + ks32*8 + cl8] = acc[b];
    __syncthreads();
    if (tt < 128) {
        int cla = tt & 7, b = tt >> 3;
        float a = 0.f;
#pragma unroll
        for (int s = 0; s < 32; s++) a += red[b*256 + s*8 + cla];
        int hh = j*8 + cla;
        g_attnA[((t+1)&1)*BH + b*H_ + hh] = a;
        g_dec_out[(size_t)(b*T_ + t)*H_ + hh] = (t < dec_len[b]) ? a : 0.f;
    }
}

// ---------------- big SGEMM: 128x128 tile, BK=8, 8x8 microtile ------------
// mode 0: keys = g_mem @ Bm           (N=1024,  K=1024, C=g_keys)
// mode 1: out  = g_dec_out @ Bm       (N=32000, K=1024, C=Cext)
// mode 2: zpre_enc = g_qemb @ Bm      (N=4096,  K=256)
// mode 3: zpre_dec = g_remb @ Bm      (N=4096,  K=256)
__global__ __launch_bounds__(256, 2) void sgemm128(int mode,
                                                   const float* __restrict__ Bm,
                                                   float* __restrict__ Cext,
                                                   int N, int K) {
    const float* A; float* C;
    if (mode == 0)      { A = g_mem;     C = g_keys; }
    else if (mode == 1) { A = g_dec_out; C = Cext; }
    else if (mode == 2) { A = g_qemb;    C = g_zpre_enc; }
    else                { A = g_remb;    C = g_zpre_dec; }

    __shared__ __align__(16) float As[2][8][132];
    __shared__ __align__(16) float Bs[2][8][128];
    const int tid = threadIdx.x;
    const int m0 = blockIdx.y * 128, n0 = blockIdx.x * 128;
    const int tx = tid & 15, ty = tid >> 4;
    const int la_r = tid >> 1, la_c = (tid & 1) * 4;
    const int lb_r = tid >> 5, lb_c = (tid & 31) * 4;

    float acc[8][8];
#pragma unroll
    for (int i = 0; i < 8; i++)
#pragma unroll
        for (int j = 0; j < 8; j++) acc[i][j] = 0.f;

    {
        float4 a4 = *(const float4*)(A  + (size_t)(m0 + la_r) * K + la_c);
        float4 b4 = *(const float4*)(Bm + (size_t)lb_r * N + n0 + lb_c);
        As[0][la_c+0][la_r] = a4.x; As[0][la_c+1][la_r] = a4.y;
        As[0][la_c+2][la_r] = a4.z; As[0][la_c+3][la_r] = a4.w;
        *(float4*)&Bs[0][lb_r][lb_c] = b4;
    }
    __syncthreads();

    const int nk = K / 8;
    for (int kt = 0; kt < nk; kt++) {
        const int cur = kt & 1;
        float4 a4n, b4n;
        const bool nx = (kt + 1) < nk;
        if (nx) {
            int kb = (kt + 1) * 8;
            a4n = *(const float4*)(A  + (size_t)(m0 + la_r) * K + kb + la_c);
            b4n = *(const float4*)(Bm + (size_t)(kb + lb_r) * N + n0 + lb_c);
        }
#pragma unroll
        for (int k = 0; k < 8; k++) {
            const float* asr = &As[cur][k][0];
            const float* bsr = &Bs[cur][k][0];
            float4 x0 = *(const float4*)(asr + ty*4);
            float4 x1 = *(const float4*)(asr + 64 + ty*4);
            float4 y0 = *(const float4*)(bsr + tx*4);
            float4 y1 = *(const float4*)(bsr + 64 + tx*4);
            float xa[8] = {x0.x,x0.y,x0.z,x0.w,x1.x,x1.y,x1.z,x1.w};
            float yb[8] = {y0.x,y0.y,y0.z,y0.w,y1.x,y1.y,y1.z,y1.w};
#pragma unroll
            for (int i = 0; i < 8; i++)
#pragma unroll
                for (int j = 0; j < 8; j++)
                    acc[i][j] += xa[i] * yb[j];
        }
        if (nx) {
            const int nxt = cur ^ 1;
            As[nxt][la_c+0][la_r] = a4n.x; As[nxt][la_c+1][la_r] = a4n.y;
            As[nxt][la_c+2][la_r] = a4n.z; As[nxt][la_c+3][la_r] = a4n.w;
            *(float4*)&Bs[nxt][lb_r][lb_c] = b4n;
            __syncthreads();
        }
    }

#pragma unroll
    for (int i = 0; i < 8; i++) {
        int r = m0 + ((i < 4) ? (ty*4 + i) : (64 + ty*4 + (i - 4)));
        float4 v0 = make_float4(acc[i][0], acc[i][1], acc[i][2], acc[i][3]);
        float4 v1 = make_float4(acc[i][4], acc[i][5], acc[i][6], acc[i][7]);
        *(float4*)(C + (size_t)r * N + n0 + tx*4)      = v0;
        *(float4*)(C + (size_t)r * N + n0 + 64 + tx*4) = v1;
    }
}

// ------------------------------ launcher ----------------------------------
extern "C" void kernel_launch(void* const* d_in, const int* in_sizes, int n_in,
                              void* d_out, int out_size) {
    const int*   enc_in  = (const int*)  d_in[0];
    const int*   dec_in  = (const int*)  d_in[1];
    const int*   enc_len = (const int*)  d_in[2];
    const int*   dec_len = (const int*)  d_in[3];
    const float* emb     = (const float*)d_in[4];
    const float* enc_k   = (const float*)d_in[5];
    const float* enc_b   = (const float*)d_in[6];
    const float* dec_k   = (const float*)d_in[7];
    const float* dec_b   = (const float*)d_in[8];
    const float* Wm      = (const float*)d_in[9];
    const float* Wq      = (const float*)d_in[10];
    const float* v_att   = (const float*)d_in[11];
    const float* attn_k  = (const float*)d_in[12];
    const float* out_k   = (const float*)d_in[13];
    float* out = (float*)d_out;

    // embeddings + zero state
    k_init<<<2368, 256>>>(enc_in, dec_in, emb);

    // precompute input projections for all timesteps (x-part of LSTM GEMMs)
    sgemm128<<<dim3(32, 8), 256>>>(2, enc_k, nullptr, G4, E_);
    sgemm128<<<dim3(32, 8), 256>>>(3, dec_k, nullptr, G4, E_);

    // encoder recurrence: 1 kernel/step
    for (int t = 0; t < T_; t++)
        k_enc_step<<<128, 256>>>(enc_k, enc_b, enc_len, t);

    // keys = memory @ Wm
    sgemm128<<<dim3(8, 8), 256>>>(0, Wm, nullptr, H_, H_);

    // decoder recurrence: 5 kernels/step
    for (int t = 0; t < T_; t++) {
        k_dec_stepA<<<128, 256>>>(dec_k, dec_b, t);
        k_query<<<128, 256>>>(Wq, t);
        k_scores<<<128, 256>>>(v_att);
        k_ctx<<<128, 128>>>(enc_len);
        k_attn2fin<<<128, 256>>>(attn_k, dec_len, t);
    }

    // logits = dec_out @ out_kernel
    sgemm128<<<dim3(250, 8), 256>>>(1, out_k, out, V_, H_);
}

// round 11
// speedup vs baseline: 1.5977x; 1.0264x over previous
#include <cuda_runtime.h>
#include <cuda_bf16.h>

#define B_  16
#define T_  64
#define V_  32000
#define E_  256
#define H_  1024
#define G4  4096
#define BH  (B_*H_)
#define NEGV (-1e9f)

typedef unsigned long long ull;

// ---------------- device scratch ----------------
__device__ float g_qemb[B_*T_*E_];
__device__ float g_remb[B_*T_*E_];
__device__ float g_zpre_enc[B_*T_*G4];   // 16MB: qemb @ Wx_enc
__device__ float g_zpre_dec[B_*T_*G4];   // 16MB: remb @ Wx_dec
__device__ float g_hA[2*BH];             // double-buffered h
__device__ float g_attnA[2*BH];          // double-buffered attn carry
__device__ float g_c[BH];
__device__ float g_q[BH];
__device__ float g_ctx[BH];
__device__ float g_mem[B_*T_*H_];
__device__ float g_keys[B_*T_*H_];
__device__ float g_dec_out[B_*T_*H_];
__device__ float g_scores[B_*T_];

// ---------------- math helpers ----------------
__device__ __forceinline__ float sigf(float x) {
    return 1.0f / (1.0f + __expf(-x));
}
__device__ __forceinline__ float tanh_fast(float x) {
    float ax = fabsf(x);
    float e  = __expf(2.0f * ax);
    float r  = 1.0f - 2.0f / (e + 1.0f);
    return copysignf(r, x);
}

// ---------------- packed f32x2 helpers (Blackwell FFMA2) ----------------
__device__ __forceinline__ ull pk2(float x) {
    ull v; asm("mov.b64 %0, {%1, %1};" : "=l"(v) : "f"(x)); return v;
}
__device__ __forceinline__ float2 upk(ull v) {
    float2 r; asm("mov.b64 {%0, %1}, %2;" : "=f"(r.x), "=f"(r.y) : "l"(v)); return r;
}
__device__ __forceinline__ void ffma2(ull& d, ull a, ull b) {
    asm("fma.rn.f32x2 %0, %1, %2, %0;" : "+l"(d) : "l"(a), "l"(b));
}

// ---------------- K0: embedding gather + zero state -----------------------
__global__ void k_init(const int* __restrict__ enc_in,
                       const int* __restrict__ dec_in,
                       const float* __restrict__ emb) {
    int i = blockIdx.x * 256 + threadIdx.x;
    const int NE = B_*T_*E_;           // 262144
    if (i < NE) {
        int bt = i >> 8, e = i & 255;
        g_qemb[i] = emb[(size_t)enc_in[bt] * E_ + e];
    } else if (i < 2*NE) {
        int j = i - NE;
        int bt = j >> 8, e = j & 255;
        g_remb[j] = emb[(size_t)dec_in[bt] * E_ + e];
    } else {
        int j = i - 2*NE;
        if (j < 2*BH)            g_hA[j] = 0.f;
        else if (j < 3*BH)       g_c[j - 2*BH] = 0.f;
        else if (j < 5*BH)       g_attnA[j - 3*BH] = 0.f;
    }
}

// ========== encoder step: h@Wh + zpre + bias -> gates (1 kernel) ==========
// 128 blocks x 512 threads. Block j owns gate-matched cols {g*1024+j*8+hl}.
// 16 k-slices of 64; FFMA2 over batch pairs.
__global__ __launch_bounds__(512) void k_enc_step(const float* __restrict__ W,
                                                  const float* __restrict__ bias,
                                                  const int* __restrict__ enc_len,
                                                  int t) {
    __shared__ __align__(16) float xs[256*16];   // 16KB chunk of h
    __shared__ float red[8192];                  // 32KB: [b][16 slices][32 cl]
    const int j  = blockIdx.x;
    const int tt = threadIdx.x;
    const int cl = tt & 31, ks = tt >> 5;        // ks in 0..15
    const int g  = cl >> 3, hl = cl & 7;
    const int col = g*1024 + j*8 + hl;
    const float* hbuf = g_hA + (t & 1)*BH;

    ull acc2[8];
#pragma unroll
    for (int p = 0; p < 8; p++) acc2[p] = 0ull;

#pragma unroll
    for (int c = 0; c < 4; c++) {                // K=1024 in 4x256
        __syncthreads();
        const float* src = hbuf + c*256;
#pragma unroll
        for (int r = 0; r < 8; r++) {
            int i = tt + r*512;
            int k = i >> 4, b = i & 15;
            xs[i] = src[b*H_ + k];
        }
        __syncthreads();
        const float* Wp = W + (size_t)(E_ + c*256 + ks*16) * G4 + col;
        const ull* xp = (const ull*)xs + ks*128;
        float w[16];
#pragma unroll
        for (int u = 0; u < 16; u++) w[u] = Wp[(size_t)u * G4];
#pragma unroll
        for (int u = 0; u < 16; u++) {
            ull wd = pk2(w[u]);
            const ull* x8 = xp + u*8;
#pragma unroll
            for (int p = 0; p < 8; p++) ffma2(acc2[p], wd, x8[p]);
        }
    }
    __syncthreads();
#pragma unroll
    for (int p = 0; p < 8; p++) {
        float2 f = upk(acc2[p]);
        red[(2*p  )*512 + ks*32 + cl] = f.x;
        red[(2*p+1)*512 + ks*32 + cl] = f.y;
    }
    __syncthreads();

    if (tt < 128) {
        int hh = tt & 7, b = tt >> 3;
        int c0 = j*8 + hh;
        const float* zp = g_zpre_enc + (size_t)(b*T_ + t)*G4;
        float zi = zp[c0]        + bias[c0];
        float zj = zp[1024 + c0] + bias[1024 + c0];
        float zf = zp[2048 + c0] + bias[2048 + c0];
        float zo = zp[3072 + c0] + bias[3072 + c0];
#pragma unroll
        for (int s = 0; s < 16; s++) {
            const float* r = red + b*512 + s*32;
            zi += r[hh]; zj += r[8+hh]; zf += r[16+hh]; zo += r[24+hh];
        }
        int idx = b*H_ + c0;
        float cc = g_c[idx];
        float cn = cc * sigf(zf + 1.f) + sigf(zi)*tanh_fast(zj);
        float hn = tanh_fast(cn)*sigf(zo);
        bool valid = t < enc_len[b];
        if (valid) g_c[idx] = cn;
        float* hout = g_hA + ((t+1)&1)*BH;
        hout[idx] = valid ? hn : hbuf[idx];
        g_mem[(size_t)(b*T_ + t)*H_ + c0] = valid ? hn : 0.f;
    }
}

// ========== decoder step A: [attn,h]@Wd + zpre + bias -> gates ============
__global__ __launch_bounds__(512) void k_dec_stepA(const float* __restrict__ W,
                                                   const float* __restrict__ bias,
                                                   int t) {
    __shared__ __align__(16) float xs[256*16];
    __shared__ float red[8192];
    const int j  = blockIdx.x;
    const int tt = threadIdx.x;
    const int cl = tt & 31, ks = tt >> 5;
    const int g  = cl >> 3, hl = cl & 7;
    const int col = g*1024 + j*8 + hl;
    const float* hbuf    = g_hA    + (t & 1)*BH;
    const float* attnbuf = g_attnA + (t & 1)*BH;

    ull acc2[8];
#pragma unroll
    for (int p = 0; p < 8; p++) acc2[p] = 0ull;

#pragma unroll
    for (int c = 0; c < 8; c++) {                // K=2048 in 8x256
        __syncthreads();
        const float* src = (c < 4) ? (attnbuf + c*256) : (hbuf + (c-4)*256);
#pragma unroll
        for (int r = 0; r < 8; r++) {
            int i = tt + r*512;
            int k = i >> 4, b = i & 15;
            xs[i] = src[b*H_ + k];
        }
        __syncthreads();
        const float* Wp = W + (size_t)(E_ + c*256 + ks*16) * G4 + col;
        const ull* xp = (const ull*)xs + ks*128;
        float w[16];
#pragma unroll
        for (int u = 0; u < 16; u++) w[u] = Wp[(size_t)u * G4];
#pragma unroll
        for (int u = 0; u < 16; u++) {
            ull wd = pk2(w[u]);
            const ull* x8 = xp + u*8;
#pragma unroll
            for (int p = 0; p < 8; p++) ffma2(acc2[p], wd, x8[p]);
        }
    }
    __syncthreads();
#pragma unroll
    for (int p = 0; p < 8; p++) {
        float2 f = upk(acc2[p]);
        red[(2*p  )*512 + ks*32 + cl] = f.x;
        red[(2*p+1)*512 + ks*32 + cl] = f.y;
    }
    __syncthreads();

    if (tt < 128) {
        int hh = tt & 7, b = tt >> 3;
        int c0 = j*8 + hh;
        const float* zp = g_zpre_dec + (size_t)(b*T_ + t)*G4;
        float zi = zp[c0]        + bias[c0];
        float zj = zp[1024 + c0] + bias[1024 + c0];
        float zf = zp[2048 + c0] + bias[2048 + c0];
        float zo = zp[3072 + c0] + bias[3072 + c0];
#pragma unroll
        for (int s = 0; s < 16; s++) {
            const float* r = red + b*512 + s*32;
            zi += r[hh]; zj += r[8+hh]; zf += r[16+hh]; zo += r[24+hh];
        }
        int idx = b*H_ + c0;
        float cc = g_c[idx];
        float cn = cc * sigf(zf + 1.f) + sigf(zi)*tanh_fast(zj);
        float hn = tanh_fast(cn)*sigf(zo);
        g_c[idx] = cn;
        g_hA[((t+1)&1)*BH + idx] = hn;           // h2
    }
}

// ========== decoder: query = h2 @ Wq ======================================
__global__ __launch_bounds__(256) void k_query(const float* __restrict__ Wq, int t) {
    __shared__ __align__(16) float xs[256*16];
    __shared__ float red[4096];
    const int j  = blockIdx.x;
    const int tt = threadIdx.x;
    const int cl8 = tt & 7, ks32 = tt >> 3;
    const int colB = j*8 + cl8;
    const float* h2buf = g_hA + ((t+1)&1)*BH;

    float acc[16];
#pragma unroll
    for (int b = 0; b < 16; b++) acc[b] = 0.f;
#pragma unroll
    for (int c = 0; c < 4; c++) {                // K=1024 in 4x256
        __syncthreads();
        const float* src = h2buf + c*256;
#pragma unroll
        for (int r = 0; r < 16; r++) {
            int i = tt + r*256;
            int k = i >> 4, b = i & 15;
            xs[i] = src[b*H_ + k];
        }
        __syncthreads();
        const float* Wp = Wq + (size_t)(c*256 + ks32*8) * H_ + colB;
        const float4* xp = (const float4*)(xs + (ks32*8)*16);
        float w[8];
#pragma unroll
        for (int u = 0; u < 8; u++) w[u] = Wp[(size_t)u * H_];
#pragma unroll
        for (int u = 0; u < 8; u++) {
            float4 x0 = xp[u*4], x1 = xp[u*4+1], x2 = xp[u*4+2], x3 = xp[u*4+3];
            float ww = w[u];
            acc[0]+=x0.x*ww; acc[1]+=x0.y*ww; acc[2]+=x0.z*ww; acc[3]+=x0.w*ww;
            acc[4]+=x1.x*ww; acc[5]+=x1.y*ww; acc[6]+=x1.z*ww; acc[7]+=x1.w*ww;
            acc[8]+=x2.x*ww; acc[9]+=x2.y*ww; acc[10]+=x2.z*ww; acc[11]+=x2.w*ww;
            acc[12]+=x3.x*ww; acc[13]+=x3.y*ww; acc[14]+=x3.z*ww; acc[15]+=x3.w*ww;
        }
    }
    __syncthreads();
#pragma unroll
    for (int b = 0; b < 16; b++) red[b*256 + ks32*8 + cl8] = acc[b];
    __syncthreads();
    if (tt < 128) {
        int clq = tt & 7, b = tt >> 3;
        float q = 0.f;
#pragma unroll
        for (int s = 0; s < 32; s++) q += red[b*256 + s*8 + clq];
        g_q[b*H_ + j*8 + clq] = q;
    }
}

// ========== decoder: scores[b][t2] = v . tanh(keys + q) ===================
__global__ __launch_bounds__(256) void k_scores(const float* __restrict__ v_att) {
    const int j  = blockIdx.x;
    const int tt = threadIdx.x;
    int pair = j*8 + (tt >> 5);                  // 1024 (b,t2) pairs
    int b = pair >> 6, t2 = pair & 63;
    int lane = tt & 31;
    const float* kr = g_keys + (size_t)(b*T_ + t2)*H_;
    const float* qr = g_q + b*H_;
    float s = 0.f;
#pragma unroll 8
    for (int h = lane; h < H_; h += 32)
        s += tanh_fast(kr[h] + qr[h]) * v_att[h];
#pragma unroll
    for (int o = 16; o > 0; o >>= 1) s += __shfl_xor_sync(0xffffffffu, s, o);
    if (lane == 0) g_scores[b*T_ + t2] = s;
}

// ========== decoder: softmax + context ====================================
__global__ __launch_bounds__(128) void k_ctx(const int* __restrict__ enc_len) {
    const int j  = blockIdx.x;
    const int tt = threadIdx.x;
    __shared__ float al[64];
    int b = j >> 3, h0 = (j & 7) * 128;
    if (tt < 32) {
        int L = enc_len[b];
        float s0 = (tt      < L) ? g_scores[b*T_ + tt]      : NEGV;
        float s1 = (tt + 32 < L) ? g_scores[b*T_ + tt + 32] : NEGV;
        float m = fmaxf(s0, s1);
#pragma unroll
        for (int o = 16; o > 0; o >>= 1) m = fmaxf(m, __shfl_xor_sync(0xffffffffu, m, o));
        float e0 = __expf(s0 - m), e1 = __expf(s1 - m);
        float ss = e0 + e1;
#pragma unroll
        for (int o = 16; o > 0; o >>= 1) ss += __shfl_xor_sync(0xffffffffu, ss, o);
        float inv = 1.f / ss;
        al[tt] = e0 * inv; al[tt + 32] = e1 * inv;
    }
    __syncthreads();
    int h = h0 + tt;
    const float* mb = g_mem + (size_t)b*T_*H_ + h;
    float a = 0.f;
#pragma unroll
    for (int t2 = 0; t2 < T_; t2++) a += al[t2] * mb[(size_t)t2 * H_];
    g_ctx[b*H_ + h] = a;
}

// ========== decoder: attn2 = [h2, ctx] @ Wa + finish ======================
__global__ __launch_bounds__(256) void k_attn2fin(const float* __restrict__ Wa,
                                                  const int* __restrict__ dec_len,
                                                  int t) {
    __shared__ __align__(16) float xs[256*16];
    __shared__ float red[4096];
    const int j  = blockIdx.x;
    const int tt = threadIdx.x;
    const int cl8 = tt & 7, ks32 = tt >> 3;
    const int colB = j*8 + cl8;
    const float* h2buf = g_hA + ((t+1)&1)*BH;

    float acc[16];
#pragma unroll
    for (int b = 0; b < 16; b++) acc[b] = 0.f;
#pragma unroll
    for (int c = 0; c < 8; c++) {                // K=2048 in 8x256
        __syncthreads();
        const float* src = (c < 4) ? (h2buf + c*256) : (g_ctx + (c-4)*256);
#pragma unroll
        for (int r = 0; r < 16; r++) {
            int i = tt + r*256;
            int k = i >> 4, b = i & 15;
            xs[i] = src[b*H_ + k];
        }
        __syncthreads();
        const float* Wp = Wa + (size_t)(c*256 + ks32*8) * H_ + colB;
        const float4* xp = (const float4*)(xs + (ks32*8)*16);
        float w[8];
#pragma unroll
        for (int u = 0; u < 8; u++) w[u] = Wp[(size_t)u * H_];
#pragma unroll
        for (int u = 0; u < 8; u++) {
            float4 x0 = xp[u*4], x1 = xp[u*4+1], x2 = xp[u*4+2], x3 = xp[u*4+3];
            float ww = w[u];
            acc[0]+=x0.x*ww; acc[1]+=x0.y*ww; acc[2]+=x0.z*ww; acc[3]+=x0.w*ww;
            acc[4]+=x1.x*ww; acc[5]+=x1.y*ww; acc[6]+=x1.z*ww; acc[7]+=x1.w*ww;
            acc[8]+=x2.x*ww; acc[9]+=x2.y*ww; acc[10]+=x2.z*ww; acc[11]+=x2.w*ww;
            acc[12]+=x3.x*ww; acc[13]+=x3.y*ww; acc[14]+=x3.z*ww; acc[15]+=x3.w*ww;
        }
    }
    __syncthreads();
#pragma unroll
    for (int b = 0; b < 16; b++) red[b*256 + ks32*8 + cl8] = acc[b];
    __syncthreads();
    if (tt < 128) {
        int cla = tt & 7, b = tt >> 3;
        float a = 0.f;
#pragma unroll
        for (int s = 0; s < 32; s++) a += red[b*256 + s*8 + cla];
        int hh = j*8 + cla;
        g_attnA[((t+1)&1)*BH + b*H_ + hh] = a;
        g_dec_out[(size_t)(b*T_ + t)*H_ + hh] = (t < dec_len[b]) ? a : 0.f;
    }
}

// ---------------- big SGEMM with FFMA2: 128x128 tile, BK=8 ----------------
// A stored duplicated in smem: As[k][2r]=As[k][2r+1]=A[r][k] -> 64-bit (a,a)
// mode 0: keys = g_mem @ Bm      mode 1: out = g_dec_out @ Bm
// mode 2: zpre_enc = g_qemb @ Bm mode 3: zpre_dec = g_remb @ Bm
__global__ __launch_bounds__(256, 2) void sgemm128(int mode,
                                                   const float* __restrict__ Bm,
                                                   float* __restrict__ Cext,
                                                   int N, int K) {
    const float* A; float* C;
    if (mode == 0)      { A = g_mem;     C = g_keys; }
    else if (mode == 1) { A = g_dec_out; C = Cext; }
    else if (mode == 2) { A = g_qemb;    C = g_zpre_enc; }
    else                { A = g_remb;    C = g_zpre_dec; }

    __shared__ __align__(16) float As[2][8][264];   // duplicated pairs (2*128 + pad)
    __shared__ __align__(16) float Bs[2][8][128];
    const int tid = threadIdx.x;
    const int m0 = blockIdx.y * 128, n0 = blockIdx.x * 128;
    const int tx = tid & 15, ty = tid >> 4;
    const int la_r = tid >> 1, la_c = (tid & 1) * 4;
    const int lb_r = tid >> 5, lb_c = (tid & 31) * 4;

    ull acc2[8][4];
#pragma unroll
    for (int i = 0; i < 8; i++)
#pragma unroll
        for (int jp = 0; jp < 4; jp++) acc2[i][jp] = 0ull;

    {   // preload tile 0 (duplicated A store)
        float4 a4 = *(const float4*)(A  + (size_t)(m0 + la_r) * K + la_c);
        float4 b4 = *(const float4*)(Bm + (size_t)lb_r * N + n0 + lb_c);
        *(float2*)&As[0][la_c+0][2*la_r] = make_float2(a4.x, a4.x);
        *(float2*)&As[0][la_c+1][2*la_r] = make_float2(a4.y, a4.y);
        *(float2*)&As[0][la_c+2][2*la_r] = make_float2(a4.z, a4.z);
        *(float2*)&As[0][la_c+3][2*la_r] = make_float2(a4.w, a4.w);
        *(float4*)&Bs[0][lb_r][lb_c] = b4;
    }
    __syncthreads();

    const int nk = K / 8;
    for (int kt = 0; kt < nk; kt++) {
        const int cur = kt & 1;
        float4 a4n, b4n;
        const bool nx = (kt + 1) < nk;
        if (nx) {
            int kb = (kt + 1) * 8;
            a4n = *(const float4*)(A  + (size_t)(m0 + la_r) * K + kb + la_c);
            b4n = *(const float4*)(Bm + (size_t)(kb + lb_r) * N + n0 + lb_c);
        }
#pragma unroll
        for (int k = 0; k < 8; k++) {
            const ull* ap = (const ull*)&As[cur][k][0];
            const ull* bp = (const ull*)&Bs[cur][k][0];
            ull av[8], bv[4];
#pragma unroll
            for (int i = 0; i < 4; i++) {
                av[i]   = ap[ty*4 + i];
                av[4+i] = ap[64 + ty*4 + i];
            }
            bv[0] = bp[tx*2];      bv[1] = bp[tx*2 + 1];
            bv[2] = bp[32 + tx*2]; bv[3] = bp[32 + tx*2 + 1];
#pragma unroll
            for (int i = 0; i < 8; i++)
#pragma unroll
                for (int jp = 0; jp < 4; jp++)
                    ffma2(acc2[i][jp], av[i], bv[jp]);
        }
        if (nx) {
            const int nxt = cur ^ 1;
            *(float2*)&As[nxt][la_c+0][2*la_r] = make_float2(a4n.x, a4n.x);
            *(float2*)&As[nxt][la_c+1][2*la_r] = make_float2(a4n.y, a4n.y);
            *(float2*)&As[nxt][la_c+2][2*la_r] = make_float2(a4n.z, a4n.z);
            *(float2*)&As[nxt][la_c+3][2*la_r] = make_float2(a4n.w, a4n.w);
            *(float4*)&Bs[nxt][lb_r][lb_c] = b4n;
            __syncthreads();
        }
    }

#pragma unroll
    for (int i = 0; i < 8; i++) {
        int r = m0 + ((i < 4) ? (ty*4 + i) : (64 + ty*4 + (i - 4)));
        float2 p0 = upk(acc2[i][0]), p1 = upk(acc2[i][1]);
        float2 p2 = upk(acc2[i][2]), p3 = upk(acc2[i][3]);
        float4 v0 = make_float4(p0.x, p0.y, p1.x, p1.y);
        float4 v1 = make_float4(p2.x, p2.y, p3.x, p3.y);
        *(float4*)(C + (size_t)r * N + n0 + tx*4)      = v0;
        *(float4*)(C + (size_t)r * N + n0 + 64 + tx*4) = v1;
    }
}

// ------------------------------ launcher ----------------------------------
extern "C" void kernel_launch(void* const* d_in, const int* in_sizes, int n_in,
                              void* d_out, int out_size) {
    const int*   enc_in  = (const int*)  d_in[0];
    const int*   dec_in  = (const int*)  d_in[1];
    const int*   enc_len = (const int*)  d_in[2];
    const int*   dec_len = (const int*)  d_in[3];
    const float* emb     = (const float*)d_in[4];
    const float* enc_k   = (const float*)d_in[5];
    const float* enc_b   = (const float*)d_in[6];
    const float* dec_k   = (const float*)d_in[7];
    const float* dec_b   = (const float*)d_in[8];
    const float* Wm      = (const float*)d_in[9];
    const float* Wq      = (const float*)d_in[10];
    const float* v_att   = (const float*)d_in[11];
    const float* attn_k  = (const float*)d_in[12];
    const float* out_k   = (const float*)d_in[13];
    float* out = (float*)d_out;

    // embeddings + zero state
    k_init<<<2368, 256>>>(enc_in, dec_in, emb);

    // precompute input projections for all timesteps
    sgemm128<<<dim3(32, 8), 256>>>(2, enc_k, nullptr, G4, E_);
    sgemm128<<<dim3(32, 8), 256>>>(3, dec_k, nullptr, G4, E_);

    // encoder recurrence: 1 kernel/step
    for (int t = 0; t < T_; t++)
        k_enc_step<<<128, 512>>>(enc_k, enc_b, enc_len, t);

    // keys = memory @ Wm
    sgemm128<<<dim3(8, 8), 256>>>(0, Wm, nullptr, H_, H_);

    // decoder recurrence: 5 kernels/step
    for (int t = 0; t < T_; t++) {
        k_dec_stepA<<<128, 512>>>(dec_k, dec_b, t);
        k_query<<<128, 256>>>(Wq, t);
        k_scores<<<128, 256>>>(v_att);
        k_ctx<<<128, 128>>>(enc_len);
        k_attn2fin<<<128, 256>>>(attn_k, dec_len, t);
    }

    // logits = dec_out @ out_kernel
    sgemm128<<<dim3(250, 8), 256>>>(1, out_k, out, V_, H_);
}

// round 13
// speedup vs baseline: 1.8178x; 1.1378x over previous
#include <cuda_runtime.h>
#include <cuda_bf16.h>
#include <cstdint>

#define B_  16
#define T_  64
#define V_  32000
#define E_  256
#define H_  1024
#define G4  4096
#define BH  (B_*H_)
#define NEGV (-1e9f)

typedef unsigned long long ull;

// ---------------- device scratch ----------------
__device__ float g_qemb[B_*T_*E_];
__device__ float g_remb[B_*T_*E_];
__device__ float g_zpre_enc[B_*T_*G4];
__device__ float g_zpre_dec[B_*T_*G4];
__device__ float g_hA[2*BH];
__device__ float g_attnA[2*BH];
__device__ float g_c[BH];
__device__ float g_q[BH];
__device__ float g_ctx[BH];
__device__ float g_mem[B_*T_*H_];
__device__ float g_keys[B_*T_*H_];
__device__ float g_dec_out[B_*T_*H_];
__device__ float g_scores[B_*T_];
__device__ __nv_bfloat16 g_Ahi[B_*T_*H_];
__device__ __nv_bfloat16 g_Alo[B_*T_*H_];

// ---------------- math helpers ----------------
__device__ __forceinline__ float sigf(float x) {
    return 1.0f / (1.0f + __expf(-x));
}
__device__ __forceinline__ float tanh_fast(float x) {
    float ax = fabsf(x);
    float e  = __expf(2.0f * ax);
    float r  = 1.0f - 2.0f / (e + 1.0f);
    return copysignf(r, x);
}

// ---------------- packed f32x2 helpers ----------------
__device__ __forceinline__ ull pk2(float x) {
    ull v; asm("mov.b64 %0, {%1, %1};" : "=l"(v) : "f"(x)); return v;
}
__device__ __forceinline__ float2 upk(ull v) {
    float2 r; asm("mov.b64 {%0, %1}, %2;" : "=f"(r.x), "=f"(r.y) : "l"(v)); return r;
}
__device__ __forceinline__ void ffma2(ull& d, ull a, ull b) {
    asm("fma.rn.f32x2 %0, %1, %2, %0;" : "+l"(d) : "l"(a), "l"(b));
}

// ---------------- mma/ldmatrix helpers ----------------
__device__ __forceinline__ void ldm_x4(uint32_t* r, uint32_t addr) {
    asm volatile("ldmatrix.sync.aligned.m8n8.x4.shared.b16 {%0,%1,%2,%3}, [%4];"
                 : "=r"(r[0]), "=r"(r[1]), "=r"(r[2]), "=r"(r[3]) : "r"(addr));
}
__device__ __forceinline__ void ldm_x4t(uint32_t* r, uint32_t addr) {
    asm volatile("ldmatrix.sync.aligned.m8n8.x4.trans.shared.b16 {%0,%1,%2,%3}, [%4];"
                 : "=r"(r[0]), "=r"(r[1]), "=r"(r[2]), "=r"(r[3]) : "r"(addr));
}
__device__ __forceinline__ void mma_bf16(float* d, const uint32_t* a,
                                         uint32_t b0, uint32_t b1) {
    asm volatile("mma.sync.aligned.m16n8k16.row.col.f32.bf16.bf16.f32 "
                 "{%0,%1,%2,%3}, {%4,%5,%6,%7}, {%8,%9}, {%0,%1,%2,%3};"
                 : "+f"(d[0]), "+f"(d[1]), "+f"(d[2]), "+f"(d[3])
                 : "r"(a[0]), "r"(a[1]), "r"(a[2]), "r"(a[3]), "r"(b0), "r"(b1));
}
__device__ __forceinline__ uint32_t pack_bf16x2(__nv_bfloat16 a, __nv_bfloat16 b) {
    return ((uint32_t)__bfloat16_as_ushort(b) << 16) | (uint32_t)__bfloat16_as_ushort(a);
}

// ---------------- K0: embedding gather + zero state -----------------------
__global__ void k_init(const int* __restrict__ enc_in,
                       const int* __restrict__ dec_in,
                       const float* __restrict__ emb) {
    int i = blockIdx.x * 256 + threadIdx.x;
    const int NE = B_*T_*E_;
    if (i < NE) {
        int bt = i >> 8, e = i & 255;
        g_qemb[i] = emb[(size_t)enc_in[bt] * E_ + e];
    } else if (i < 2*NE) {
        int j = i - NE;
        int bt = j >> 8, e = j & 255;
        g_remb[j] = emb[(size_t)dec_in[bt] * E_ + e];
    } else {
        int j = i - 2*NE;
        if (j < 2*BH)            g_hA[j] = 0.f;
        else if (j < 3*BH)       g_c[j - 2*BH] = 0.f;
        else if (j < 5*BH)       g_attnA[j - 3*BH] = 0.f;
    }
}

// ========== encoder step ==========
__global__ __launch_bounds__(512) void k_enc_step(const float* __restrict__ W,
                                                  const float* __restrict__ bias,
                                                  const int* __restrict__ enc_len,
                                                  int t) {
    __shared__ __align__(16) float xs[256*16];
    __shared__ float red[8192];
    const int j  = blockIdx.x;
    const int tt = threadIdx.x;
    const int cl = tt & 31, ks = tt >> 5;
    const int g  = cl >> 3, hl = cl & 7;
    const int col = g*1024 + j*8 + hl;
    const float* hbuf = g_hA + (t & 1)*BH;

    ull acc2[8];
#pragma unroll
    for (int p = 0; p < 8; p++) acc2[p] = 0ull;

#pragma unroll
    for (int c = 0; c < 4; c++) {
        __syncthreads();
        const float* src = hbuf + c*256;
#pragma unroll
        for (int r = 0; r < 8; r++) {
            int i = tt + r*512;
            int k = i >> 4, b = i & 15;
            xs[i] = src[b*H_ + k];
        }
        __syncthreads();
        const float* Wp = W + (size_t)(E_ + c*256 + ks*16) * G4 + col;
        const ull* xp = (const ull*)xs + ks*128;
        float w[16];
#pragma unroll
        for (int u = 0; u < 16; u++) w[u] = Wp[(size_t)u * G4];
#pragma unroll
        for (int u = 0; u < 16; u++) {
            ull wd = pk2(w[u]);
            const ull* x8 = xp + u*8;
#pragma unroll
            for (int p = 0; p < 8; p++) ffma2(acc2[p], wd, x8[p]);
        }
    }
    __syncthreads();
#pragma unroll
    for (int p = 0; p < 8; p++) {
        float2 f = upk(acc2[p]);
        red[(2*p  )*512 + ks*32 + cl] = f.x;
        red[(2*p+1)*512 + ks*32 + cl] = f.y;
    }
    __syncthreads();

    if (tt < 128) {
        int hh = tt & 7, b = tt >> 3;
        int c0 = j*8 + hh;
        const float* zp = g_zpre_enc + (size_t)(b*T_ + t)*G4;
        float zi = zp[c0]        + bias[c0];
        float zj = zp[1024 + c0] + bias[1024 + c0];
        float zf = zp[2048 + c0] + bias[2048 + c0];
        float zo = zp[3072 + c0] + bias[3072 + c0];
#pragma unroll
        for (int s = 0; s < 16; s++) {
            const float* r = red + b*512 + s*32;
            zi += r[hh]; zj += r[8+hh]; zf += r[16+hh]; zo += r[24+hh];
        }
        int idx = b*H_ + c0;
        float cc = g_c[idx];
        float cn = cc * sigf(zf + 1.f) + sigf(zi)*tanh_fast(zj);
        float hn = tanh_fast(cn)*sigf(zo);
        bool valid = t < enc_len[b];
        if (valid) g_c[idx] = cn;
        float* hout = g_hA + ((t+1)&1)*BH;
        hout[idx] = valid ? hn : hbuf[idx];
        g_mem[(size_t)(b*T_ + t)*H_ + c0] = valid ? hn : 0.f;
    }
}

// ========== decoder step A ==========
__global__ __launch_bounds__(512) void k_dec_stepA(const float* __restrict__ W,
                                                   const float* __restrict__ bias,
                                                   int t) {
    __shared__ __align__(16) float xs[256*16];
    __shared__ float red[8192];
    const int j  = blockIdx.x;
    const int tt = threadIdx.x;
    const int cl = tt & 31, ks = tt >> 5;
    const int g  = cl >> 3, hl = cl & 7;
    const int col = g*1024 + j*8 + hl;
    const float* hbuf    = g_hA    + (t & 1)*BH;
    const float* attnbuf = g_attnA + (t & 1)*BH;

    ull acc2[8];
#pragma unroll
    for (int p = 0; p < 8; p++) acc2[p] = 0ull;

#pragma unroll
    for (int c = 0; c < 8; c++) {
        __syncthreads();
        const float* src = (c < 4) ? (attnbuf + c*256) : (hbuf + (c-4)*256);
#pragma unroll
        for (int r = 0; r < 8; r++) {
            int i = tt + r*512;
            int k = i >> 4, b = i & 15;
            xs[i] = src[b*H_ + k];
        }
        __syncthreads();
        const float* Wp = W + (size_t)(E_ + c*256 + ks*16) * G4 + col;
        const ull* xp = (const ull*)xs + ks*128;
        float w[16];
#pragma unroll
        for (int u = 0; u < 16; u++) w[u] = Wp[(size_t)u * G4];
#pragma unroll
        for (int u = 0; u < 16; u++) {
            ull wd = pk2(w[u]);
            const ull* x8 = xp + u*8;
#pragma unroll
            for (int p = 0; p < 8; p++) ffma2(acc2[p], wd, x8[p]);
        }
    }
    __syncthreads();
#pragma unroll
    for (int p = 0; p < 8; p++) {
        float2 f = upk(acc2[p]);
        red[(2*p  )*512 + ks*32 + cl] = f.x;
        red[(2*p+1)*512 + ks*32 + cl] = f.y;
    }
    __syncthreads();

    if (tt < 128) {
        int hh = tt & 7, b = tt >> 3;
        int c0 = j*8 + hh;
        const float* zp = g_zpre_dec + (size_t)(b*T_ + t)*G4;
        float zi = zp[c0]        + bias[c0];
        float zj = zp[1024 + c0] + bias[1024 + c0];
        float zf = zp[2048 + c0] + bias[2048 + c0];
        float zo = zp[3072 + c0] + bias[3072 + c0];
#pragma unroll
        for (int s = 0; s < 16; s++) {
            const float* r = red + b*512 + s*32;
            zi += r[hh]; zj += r[8+hh]; zf += r[16+hh]; zo += r[24+hh];
        }
        int idx = b*H_ + c0;
        float cc = g_c[idx];
        float cn = cc * sigf(zf + 1.f) + sigf(zi)*tanh_fast(zj);
        float hn = tanh_fast(cn)*sigf(zo);
        g_c[idx] = cn;
        g_hA[((t+1)&1)*BH + idx] = hn;
    }
}

// ========== decoder: query = h2 @ Wq ==========
__global__ __launch_bounds__(256) void k_query(const float* __restrict__ Wq, int t) {
    __shared__ __align__(16) float xs[256*16];
    __shared__ float red[4096];
    const int j  = blockIdx.x;
    const int tt = threadIdx.x;
    const int cl8 = tt & 7, ks32 = tt >> 3;
    const int colB = j*8 + cl8;
    const float* h2buf = g_hA + ((t+1)&1)*BH;

    float acc[16];
#pragma unroll
    for (int b = 0; b < 16; b++) acc[b] = 0.f;
#pragma unroll
    for (int c = 0; c < 4; c++) {
        __syncthreads();
        const float* src = h2buf + c*256;
#pragma unroll
        for (int r = 0; r < 16; r++) {
            int i = tt + r*256;
            int k = i >> 4, b = i & 15;
            xs[i] = src[b*H_ + k];
        }
        __syncthreads();
        const float* Wp = Wq + (size_t)(c*256 + ks32*8) * H_ + colB;
        const float4* xp = (const float4*)(xs + (ks32*8)*16);
        float w[8];
#pragma unroll
        for (int u = 0; u < 8; u++) w[u] = Wp[(size_t)u * H_];
#pragma unroll
        for (int u = 0; u < 8; u++) {
            float4 x0 = xp[u*4], x1 = xp[u*4+1], x2 = xp[u*4+2], x3 = xp[u*4+3];
            float ww = w[u];
            acc[0]+=x0.x*ww; acc[1]+=x0.y*ww; acc[2]+=x0.z*ww; acc[3]+=x0.w*ww;
            acc[4]+=x1.x*ww; acc[5]+=x1.y*ww; acc[6]+=x1.z*ww; acc[7]+=x1.w*ww;
            acc[8]+=x2.x*ww; acc[9]+=x2.y*ww; acc[10]+=x2.z*ww; acc[11]+=x2.w*ww;
            acc[12]+=x3.x*ww; acc[13]+=x3.y*ww; acc[14]+=x3.z*ww; acc[15]+=x3.w*ww;
        }
    }
    __syncthreads();
#pragma unroll
    for (int b = 0; b < 16; b++) red[b*256 + ks32*8 + cl8] = acc[b];
    __syncthreads();
    if (tt < 128) {
        int clq = tt & 7, b = tt >> 3;
        float q = 0.f;
#pragma unroll
        for (int s = 0; s < 32; s++) q += red[b*256 + s*8 + clq];
        g_q[b*H_ + j*8 + clq] = q;
    }
}

// ========== decoder: scores ==========
__global__ __launch_bounds__(256) void k_scores(const float* __restrict__ v_att) {
    const int j  = blockIdx.x;
    const int tt = threadIdx.x;
    int pair = j*8 + (tt >> 5);
    int b = pair >> 6, t2 = pair & 63;
    int lane = tt & 31;
    const float* kr = g_keys + (size_t)(b*T_ + t2)*H_;
    const float* qr = g_q + b*H_;
    float s = 0.f;
#pragma unroll 8
    for (int h = lane; h < H_; h += 32)
        s += tanh_fast(kr[h] + qr[h]) * v_att[h];
#pragma unroll
    for (int o = 16; o > 0; o >>= 1) s += __shfl_xor_sync(0xffffffffu, s, o);
    if (lane == 0) g_scores[b*T_ + t2] = s;
}

// ========== decoder: softmax + context ==========
__global__ __launch_bounds__(128) void k_ctx(const int* __restrict__ enc_len) {
    const int j  = blockIdx.x;
    const int tt = threadIdx.x;
    __shared__ float al[64];
    int b = j >> 3, h0 = (j & 7) * 128;
    if (tt < 32) {
        int L = enc_len[b];
        float s0 = (tt      < L) ? g_scores[b*T_ + tt]      : NEGV;
        float s1 = (tt + 32 < L) ? g_scores[b*T_ + tt + 32] : NEGV;
        float m = fmaxf(s0, s1);
#pragma unroll
        for (int o = 16; o > 0; o >>= 1) m = fmaxf(m, __shfl_xor_sync(0xffffffffu, m, o));
        float e0 = __expf(s0 - m), e1 = __expf(s1 - m);
        float ss = e0 + e1;
#pragma unroll
        for (int o = 16; o > 0; o >>= 1) ss += __shfl_xor_sync(0xffffffffu, ss, o);
        float inv = 1.f / ss;
        al[tt] = e0 * inv; al[tt + 32] = e1 * inv;
    }
    __syncthreads();
    int h = h0 + tt;
    const float* mb = g_mem + (size_t)b*T_*H_ + h;
    float a = 0.f;
#pragma unroll
    for (int t2 = 0; t2 < T_; t2++) a += al[t2] * mb[(size_t)t2 * H_];
    g_ctx[b*H_ + h] = a;
}

// ========== decoder: attn2 + finish ==========
__global__ __launch_bounds__(256) void k_attn2fin(const float* __restrict__ Wa,
                                                  const int* __restrict__ dec_len,
                                                  int t) {
    __shared__ __align__(16) float xs[256*16];
    __shared__ float red[4096];
    const int j  = blockIdx.x;
    const int tt = threadIdx.x;
    const int cl8 = tt & 7, ks32 = tt >> 3;
    const int colB = j*8 + cl8;
    const float* h2buf = g_hA + ((t+1)&1)*BH;

    float acc[16];
#pragma unroll
    for (int b = 0; b < 16; b++) acc[b] = 0.f;
#pragma unroll
    for (int c = 0; c < 8; c++) {
        __syncthreads();
        const float* src = (c < 4) ? (h2buf + c*256) : (g_ctx + (c-4)*256);
#pragma unroll
        for (int r = 0; r < 16; r++) {
            int i = tt + r*256;
            int k = i >> 4, b = i & 15;
            xs[i] = src[b*H_ + k];
        }
        __syncthreads();
        const float* Wp = Wa + (size_t)(c*256 + ks32*8) * H_ + colB;
        const float4* xp = (const float4*)(xs + (ks32*8)*16);
        float w[8];
#pragma unroll
        for (int u = 0; u < 8; u++) w[u] = Wp[(size_t)u * H_];
#pragma unroll
        for (int u = 0; u < 8; u++) {
            float4 x0 = xp[u*4], x1 = xp[u*4+1], x2 = xp[u*4+2], x3 = xp[u*4+3];
            float ww = w[u];
            acc[0]+=x0.x*ww; acc[1]+=x0.y*ww; acc[2]+=x0.z*ww; acc[3]+=x0.w*ww;
            acc[4]+=x1.x*ww; acc[5]+=x1.y*ww; acc[6]+=x1.z*ww; acc[7]+=x1.w*ww;
            acc[8]+=x2.x*ww; acc[9]+=x2.y*ww; acc[10]+=x2.z*ww; acc[11]+=x2.w*ww;
            acc[12]+=x3.x*ww; acc[13]+=x3.y*ww; acc[14]+=x3.z*ww; acc[15]+=x3.w*ww;
        }
    }
    __syncthreads();
#pragma unroll
    for (int b = 0; b < 16; b++) red[b*256 + ks32*8 + cl8] = acc[b];
    __syncthreads();
    if (tt < 128) {
        int cla = tt & 7, b = tt >> 3;
        float a = 0.f;
#pragma unroll
        for (int s = 0; s < 32; s++) a += red[b*256 + s*8 + cla];
        int hh = j*8 + cla;
        g_attnA[((t+1)&1)*BH + b*H_ + hh] = a;
        g_dec_out[(size_t)(b*T_ + t)*H_ + hh] = (t < dec_len[b]) ? a : 0.f;
    }
}

// ---------------- FFMA2 SGEMM (keys + preprojections) ----------------
__global__ __launch_bounds__(256, 2) void sgemm128(int mode,
                                                   const float* __restrict__ Bm,
                                                   int N, int K) {
    const float* A; float* C;
    if (mode == 0)      { A = g_mem;  C = g_keys; }
    else if (mode == 2) { A = g_qemb; C = g_zpre_enc; }
    else                { A = g_remb; C = g_zpre_dec; }

    __shared__ __align__(16) float As[2][8][264];
    __shared__ __align__(16) float Bs[2][8][128];
    const int tid = threadIdx.x;
    const int m0 = blockIdx.y * 128, n0 = blockIdx.x * 128;
    const int tx = tid & 15, ty = tid >> 4;
    const int la_r = tid >> 1, la_c = (tid & 1) * 4;
    const int lb_r = tid >> 5, lb_c = (tid & 31) * 4;

    ull acc2[8][4];
#pragma unroll
    for (int i = 0; i < 8; i++) {
#pragma unroll
        for (int jp = 0; jp < 4; jp++) acc2[i][jp] = 0ull;
    }

    {
        float4 a4 = *(const float4*)(A  + (size_t)(m0 + la_r) * K + la_c);
        float4 b4 = *(const float4*)(Bm + (size_t)lb_r * N + n0 + lb_c);
        *(float2*)&As[0][la_c+0][2*la_r] = make_float2(a4.x, a4.x);
        *(float2*)&As[0][la_c+1][2*la_r] = make_float2(a4.y, a4.y);
        *(float2*)&As[0][la_c+2][2*la_r] = make_float2(a4.z, a4.z);
        *(float2*)&As[0][la_c+3][2*la_r] = make_float2(a4.w, a4.w);
        *(float4*)&Bs[0][lb_r][lb_c] = b4;
    }
    __syncthreads();

    const int nk = K / 8;
    for (int kt = 0; kt < nk; kt++) {
        const int cur = kt & 1;
        float4 a4n, b4n;
        const bool nx = (kt + 1) < nk;
        if (nx) {
            int kb = (kt + 1) * 8;
            a4n = *(const float4*)(A  + (size_t)(m0 + la_r) * K + kb + la_c);
            b4n = *(const float4*)(Bm + (size_t)(kb + lb_r) * N + n0 + lb_c);
        }
#pragma unroll
        for (int k = 0; k < 8; k++) {
            const ull* ap = (const ull*)&As[cur][k][0];
            const ull* bp = (const ull*)&Bs[cur][k][0];
            ull av[8], bv[4];
#pragma unroll
            for (int i = 0; i < 4; i++) {
                av[i]   = ap[ty*4 + i];
                av[4+i] = ap[64 + ty*4 + i];
            }
            bv[0] = bp[tx*2];      bv[1] = bp[tx*2 + 1];
            bv[2] = bp[32 + tx*2]; bv[3] = bp[32 + tx*2 + 1];
#pragma unroll
            for (int i = 0; i < 8; i++) {
#pragma unroll
                for (int jp = 0; jp < 4; jp++) ffma2(acc2[i][jp], av[i], bv[jp]);
            }
        }
        if (nx) {
            const int nxt = cur ^ 1;
            *(float2*)&As[nxt][la_c+0][2*la_r] = make_float2(a4n.x, a4n.x);
            *(float2*)&As[nxt][la_c+1][2*la_r] = make_float2(a4n.y, a4n.y);
            *(float2*)&As[nxt][la_c+2][2*la_r] = make_float2(a4n.z, a4n.z);
            *(float2*)&As[nxt][la_c+3][2*la_r] = make_float2(a4n.w, a4n.w);
            *(float4*)&Bs[nxt][lb_r][lb_c] = b4n;
            __syncthreads();
        }
    }

#pragma unroll
    for (int i = 0; i < 8; i++) {
        int r = m0 + ((i < 4) ? (ty*4 + i) : (64 + ty*4 + (i - 4)));
        float2 p0 = upk(acc2[i][0]), p1 = upk(acc2[i][1]);
        float2 p2 = upk(acc2[i][2]), p3 = upk(acc2[i][3]);
        float4 v0 = make_float4(p0.x, p0.y, p1.x, p1.y);
        float4 v1 = make_float4(p2.x, p2.y, p3.x, p3.y);
        *(float4*)(C + (size_t)r * N + n0 + tx*4)      = v0;
        *(float4*)(C + (size_t)r * N + n0 + 64 + tx*4) = v1;
    }
}

// ================= logits on tensor cores (bf16 hi/lo split) ==============
__global__ void k_splitA() {
    int i = blockIdx.x * 512 + threadIdx.x;
    float x = g_dec_out[i];
    __nv_bfloat16 h = __float2bfloat16(x);
    g_Ahi[i] = h;
    g_Alo[i] = __float2bfloat16(x - __bfloat162float(h));
}

// C[1024,32000] = A @ W. Block tile 256x128, 512 threads (4x4 warps),
// warp tile 64x32, k-step 16, double buffered, 3-pass hi/lo mma.
// smem: Ahi 2*256*24 bf16 (24576 B) | Alo (24576 B) |
//       Whi 2*16*136 bf16 (8704 B)  | Wlo (8704 B)  = 66560 B total
__global__ __launch_bounds__(512, 1) void k_logits(const float* __restrict__ Wk,
                                                   float* __restrict__ C) {
    extern __shared__ char smbuf[];
    __nv_bfloat16* sAhi = (__nv_bfloat16*)(smbuf);
    __nv_bfloat16* sAlo = (__nv_bfloat16*)(smbuf + 24576);
    __nv_bfloat16* sWhi = (__nv_bfloat16*)(smbuf + 49152);
    __nv_bfloat16* sWlo = (__nv_bfloat16*)(smbuf + 57856);
    const int tid  = threadIdx.x;
    const int lane = tid & 31;
    const int warp = tid >> 5;
    const int wm = warp & 3;
    const int wn = warp >> 2;
    const int n0 = blockIdx.x * 128;
    const int m0 = blockIdx.y * 256;
    const int ar = tid >> 1;
    const int ac = (tid & 1) * 8;
    const int wr = tid >> 5;
    const int wc = (tid & 31) * 4;

    const uint32_t uAhi = (uint32_t)__cvta_generic_to_shared(sAhi);
    const uint32_t uAlo = (uint32_t)__cvta_generic_to_shared(sAlo);
    const uint32_t uWhi = (uint32_t)__cvta_generic_to_shared(sWhi);
    const uint32_t uWlo = (uint32_t)__cvta_generic_to_shared(sWlo);

    const int aRow  = lane & 15;
    const int aColB = (lane >> 4) * 16;

    float acc[4][4][4];
#pragma unroll
    for (int mt = 0; mt < 4; mt++) {
#pragma unroll
        for (int nt = 0; nt < 4; nt++) {
#pragma unroll
            for (int q = 0; q < 4; q++) acc[mt][nt][q] = 0.0f;
        }
    }

    // prologue: stage k-chunk 0 into buffer 0
    {
        uint4 va = *(const uint4*)(g_Ahi + (size_t)(m0 + ar) * H_ + ac);
        uint4 vl = *(const uint4*)(g_Alo + (size_t)(m0 + ar) * H_ + ac);
        *(uint4*)(sAhi + ar * 24 + ac) = va;
        *(uint4*)(sAlo + ar * 24 + ac) = vl;
        float4 w4 = *(const float4*)(Wk + (size_t)wr * V_ + n0 + wc);
        __nv_bfloat16 h0 = __float2bfloat16(w4.x);
        __nv_bfloat16 h1 = __float2bfloat16(w4.y);
        __nv_bfloat16 h2 = __float2bfloat16(w4.z);
        __nv_bfloat16 h3 = __float2bfloat16(w4.w);
        __nv_bfloat16 l0 = __float2bfloat16(w4.x - __bfloat162float(h0));
        __nv_bfloat16 l1 = __float2bfloat16(w4.y - __bfloat162float(h1));
        __nv_bfloat16 l2 = __float2bfloat16(w4.z - __bfloat162float(h2));
        __nv_bfloat16 l3 = __float2bfloat16(w4.w - __bfloat162float(h3));
        *(uint32_t*)(sWhi + wr * 136 + wc)     = pack_bf16x2(h0, h1);
        *(uint32_t*)(sWhi + wr * 136 + wc + 2) = pack_bf16x2(h2, h3);
        *(uint32_t*)(sWlo + wr * 136 + wc)     = pack_bf16x2(l0, l1);
        *(uint32_t*)(sWlo + wr * 136 + wc + 2) = pack_bf16x2(l2, l3);
    }
    __syncthreads();

    for (int kt = 0; kt < 64; kt++) {
        const int buf = kt & 1;
        const bool has = (kt < 63);
        uint4 na, nl;
        float4 nw;
        if (has) {
            int kn = (kt + 1) * 16;
            na = *(const uint4*)(g_Ahi + (size_t)(m0 + ar) * H_ + kn + ac);
            nl = *(const uint4*)(g_Alo + (size_t)(m0 + ar) * H_ + kn + ac);
            nw = *(const float4*)(Wk + (size_t)(kn + wr) * V_ + n0 + wc);
        }

        // B fragments for this warp's 32 columns (hi and lo)
        uint32_t bhi[2][4];
        uint32_t blo[2][4];
#pragma unroll
        for (int ch = 0; ch < 2; ch++) {
            uint32_t off = (uint32_t)(((buf * 16 + aRow) * 136 + wn * 32 + ch * 16) * 2 + aColB);
            ldm_x4t(bhi[ch], uWhi + off);
            ldm_x4t(blo[ch], uWlo + off);
        }

        // A fragments per m-tile, 3-pass mma
#pragma unroll
        for (int mt = 0; mt < 4; mt++) {
            uint32_t ah[4];
            uint32_t al[4];
            uint32_t off = (uint32_t)(((buf * 256 + wm * 64 + mt * 16 + aRow) * 24) * 2 + aColB);
            ldm_x4(ah, uAhi + off);
            ldm_x4(al, uAlo + off);
#pragma unroll
            for (int nt = 0; nt < 4; nt++) {
                uint32_t b0 = bhi[nt >> 1][(nt & 1) * 2];
                uint32_t b1 = bhi[nt >> 1][(nt & 1) * 2 + 1];
                uint32_t c0 = blo[nt >> 1][(nt & 1) * 2];
                uint32_t c1 = blo[nt >> 1][(nt & 1) * 2 + 1];
                mma_bf16(acc[mt][nt], ah, b0, b1);
                mma_bf16(acc[mt][nt], al, b0, b1);
                mma_bf16(acc[mt][nt], ah, c0, c1);
            }
        }

        // stage next chunk into the other buffer
        if (has) {
            const int nbuf = buf ^ 1;
            *(uint4*)(sAhi + (nbuf * 256 + ar) * 24 + ac) = na;
            *(uint4*)(sAlo + (nbuf * 256 + ar) * 24 + ac) = nl;
            __nv_bfloat16 h0 = __float2bfloat16(nw.x);
            __nv_bfloat16 h1 = __float2bfloat16(nw.y);
            __nv_bfloat16 h2 = __float2bfloat16(nw.z);
            __nv_bfloat16 h3 = __float2bfloat16(nw.w);
            __nv_bfloat16 l0 = __float2bfloat16(nw.x - __bfloat162float(h0));
            __nv_bfloat16 l1 = __float2bfloat16(nw.y - __bfloat162float(h1));
            __nv_bfloat16 l2 = __float2bfloat16(nw.z - __bfloat162float(h2));
            __nv_bfloat16 l3 = __float2bfloat16(nw.w - __bfloat162float(h3));
            *(uint32_t*)(sWhi + (nbuf * 16 + wr) * 136 + wc)     = pack_bf16x2(h0, h1);
            *(uint32_t*)(sWhi + (nbuf * 16 + wr) * 136 + wc + 2) = pack_bf16x2(h2, h3);
            *(uint32_t*)(sWlo + (nbuf * 16 + wr) * 136 + wc)     = pack_bf16x2(l0, l1);
            *(uint32_t*)(sWlo + (nbuf * 16 + wr) * 136 + wc + 2) = pack_bf16x2(l2, l3);
        }
        __syncthreads();
    }

    // epilogue
#pragma unroll
    for (int mt = 0; mt < 4; mt++) {
        int row = m0 + wm * 64 + mt * 16 + (lane >> 2);
#pragma unroll
        for (int nt = 0; nt < 4; nt++) {
            int col = n0 + wn * 32 + nt * 8 + (lane & 3) * 2;
            *(float2*)(C + (size_t)row * V_ + col) =
                make_float2(acc[mt][nt][0], acc[mt][nt][1]);
            *(float2*)(C + (size_t)(row + 8) * V_ + col) =
                make_float2(acc[mt][nt][2], acc[mt][nt][3]);
        }
    }
}

// ------------------------------ launcher ----------------------------------
extern "C" void kernel_launch(void* const* d_in, const int* in_sizes, int n_in,
                              void* d_out, int out_size) {
    const int*   enc_in  = (const int*)  d_in[0];
    const int*   dec_in  = (const int*)  d_in[1];
    const int*   enc_len = (const int*)  d_in[2];
    const int*   dec_len = (const int*)  d_in[3];
    const float* emb     = (const float*)d_in[4];
    const float* enc_k   = (const float*)d_in[5];
    const float* enc_b   = (const float*)d_in[6];
    const float* dec_k   = (const float*)d_in[7];
    const float* dec_b   = (const float*)d_in[8];
    const float* Wm      = (const float*)d_in[9];
    const float* Wq      = (const float*)d_in[10];
    const float* v_att   = (const float*)d_in[11];
    const float* attn_k  = (const float*)d_in[12];
    const float* out_k   = (const float*)d_in[13];
    float* out = (float*)d_out;

    cudaFuncSetAttribute(k_logits, cudaFuncAttributeMaxDynamicSharedMemorySize, 66560);

    // embeddings + zero state
    k_init<<<2368, 256>>>(enc_in, dec_in, emb);

    // precompute input projections for all timesteps
    sgemm128<<<dim3(32, 8), 256>>>(2, enc_k, G4, E_);
    sgemm128<<<dim3(32, 8), 256>>>(3, dec_k, G4, E_);

    // encoder recurrence
    for (int t = 0; t < T_; t++)
        k_enc_step<<<128, 512>>>(enc_k, enc_b, enc_len, t);

    // keys = memory @ Wm
    sgemm128<<<dim3(8, 8), 256>>>(0, Wm, H_, H_);

    // decoder recurrence
    for (int t = 0; t < T_; t++) {
        k_dec_stepA<<<128, 512>>>(dec_k, dec_b, t);
        k_query<<<128, 256>>>(Wq, t);
        k_scores<<<128, 256>>>(v_att);
        k_ctx<<<128, 128>>>(enc_len);
        k_attn2fin<<<128, 256>>>(attn_k, dec_len, t);
    }

    // logits on tensor cores
    k_splitA<<<2048, 512>>>();
    k_logits<<<dim3(250, 4), 512, 66560>>>(out_k, out);
}

// round 14
// speedup vs baseline: 2.3391x; 1.2867x over previous
#include <cuda_runtime.h>
#include <cuda_bf16.h>
#include <cstdint>

#define B_  16
#define T_  64
#define V_  32000
#define E_  256
#define H_  1024
#define G4  4096
#define BH  (B_*H_)
#define NBLK 128
#define NEGV (-1e9f)

typedef unsigned long long ull;

// ---------------- device scratch ----------------
__device__ float g_qemb[B_*T_*E_];
__device__ float g_remb[B_*T_*E_];
__device__ float g_zpre_enc[B_*T_*G4];
__device__ float g_zpre_dec[B_*T_*G4];
__device__ float g_hA[2*BH];
__device__ float g_attnA[2*BH];
__device__ float g_c[BH];
__device__ float g_q[BH];
__device__ float g_ctx[BH];
__device__ float g_mem[B_*T_*H_];
__device__ float g_keys[B_*T_*H_];
__device__ float g_dec_out[B_*T_*H_];
__device__ float g_scores[B_*T_];
__device__ __nv_bfloat16 g_Ahi[B_*T_*H_];
__device__ __nv_bfloat16 g_Alo[B_*T_*H_];
// barrier state
__device__ unsigned g_arrive[NBLK];
__device__ unsigned g_release;

// ---------------- math helpers ----------------
__device__ __forceinline__ float sigf(float x) {
    return 1.0f / (1.0f + __expf(-x));
}
__device__ __forceinline__ float tanh_fast(float x) {
    float ax = fabsf(x);
    float e  = __expf(2.0f * ax);
    float r  = 1.0f - 2.0f / (e + 1.0f);
    return copysignf(r, x);
}

// ---------------- packed f32x2 helpers ----------------
__device__ __forceinline__ ull pk2(float x) {
    ull v; asm("mov.b64 %0, {%1, %1};" : "=l"(v) : "f"(x)); return v;
}
__device__ __forceinline__ float2 upk(ull v) {
    float2 r; asm("mov.b64 {%0, %1}, %2;" : "=f"(r.x), "=f"(r.y) : "l"(v)); return r;
}
__device__ __forceinline__ void ffma2(ull& d, ull a, ull b) {
    asm("fma.rn.f32x2 %0, %1, %2, %0;" : "+l"(d) : "l"(a), "l"(b));
}

// ---------------- acquire/release flag ops (no fences, no IVALL) ----------
__device__ __forceinline__ void st_rel(unsigned* p, unsigned v) {
    asm volatile("st.release.gpu.b32 [%0], %1;" :: "l"(p), "r"(v) : "memory");
}
__device__ __forceinline__ unsigned ld_acq(const unsigned* p) {
    unsigned v;
    asm volatile("ld.acquire.gpu.b32 %0, [%1];" : "=r"(v) : "l"(p) : "memory");
    return v;
}

// grid barrier: all NBLK blocks resident (1 block/SM). Epoch-matched.
__device__ __forceinline__ void grid_barrier(int j, int tt, unsigned ep) {
    __syncthreads();
    if (j == 0) {
        if (tt < NBLK) {
            if (tt == 0) st_rel(&g_arrive[0], ep);
            while (ld_acq(&g_arrive[tt]) != ep) {}
        }
        __syncthreads();
        if (tt == 0) st_rel(&g_release, ep);
    } else {
        if (tt == 0) {
            st_rel(&g_arrive[j], ep);
            while (ld_acq(&g_release) != ep) {}
        }
    }
    __syncthreads();
}

// ---------------- mma/ldmatrix helpers ----------------
__device__ __forceinline__ void ldm_x4(uint32_t* r, uint32_t addr) {
    asm volatile("ldmatrix.sync.aligned.m8n8.x4.shared.b16 {%0,%1,%2,%3}, [%4];"
                 : "=r"(r[0]), "=r"(r[1]), "=r"(r[2]), "=r"(r[3]) : "r"(addr));
}
__device__ __forceinline__ void ldm_x4t(uint32_t* r, uint32_t addr) {
    asm volatile("ldmatrix.sync.aligned.m8n8.x4.trans.shared.b16 {%0,%1,%2,%3}, [%4];"
                 : "=r"(r[0]), "=r"(r[1]), "=r"(r[2]), "=r"(r[3]) : "r"(addr));
}
__device__ __forceinline__ void mma_bf16(float* d, const uint32_t* a,
                                         uint32_t b0, uint32_t b1) {
    asm volatile("mma.sync.aligned.m16n8k16.row.col.f32.bf16.bf16.f32 "
                 "{%0,%1,%2,%3}, {%4,%5,%6,%7}, {%8,%9}, {%0,%1,%2,%3};"
                 : "+f"(d[0]), "+f"(d[1]), "+f"(d[2]), "+f"(d[3])
                 : "r"(a[0]), "r"(a[1]), "r"(a[2]), "r"(a[3]), "r"(b0), "r"(b1));
}
__device__ __forceinline__ uint32_t pack_bf16x2(__nv_bfloat16 a, __nv_bfloat16 b) {
    return ((uint32_t)__bfloat16_as_ushort(b) << 16) | (uint32_t)__bfloat16_as_ushort(a);
}

// ---------------- K0: embedding gather + zero state + barrier reset -------
__global__ void k_init(const int* __restrict__ enc_in,
                       const int* __restrict__ dec_in,
                       const float* __restrict__ emb) {
    if (blockIdx.x == 0) {
        if (threadIdx.x < NBLK) g_arrive[threadIdx.x] = 0u;
        if (threadIdx.x == NBLK) g_release = 0u;
    }
    int i = blockIdx.x * 256 + threadIdx.x;
    const int NE = B_*T_*E_;
    if (i < NE) {
        int bt = i >> 8, e = i & 255;
        g_qemb[i] = emb[(size_t)enc_in[bt] * E_ + e];
    } else if (i < 2*NE) {
        int j = i - NE;
        int bt = j >> 8, e = j & 255;
        g_remb[j] = emb[(size_t)dec_in[bt] * E_ + e];
    } else {
        int j = i - 2*NE;
        if (j < 2*BH)            g_hA[j] = 0.f;
        else if (j < 3*BH)       g_c[j - 2*BH] = 0.f;
        else if (j < 5*BH)       g_attnA[j - 3*BH] = 0.f;
    }
}

// ================= persistent encoder =================
// 128 blocks x 512 threads. Block j owns gate-matched cols {g*1024+j*8+hl}.
// dyn smem: xs[16384] floats (64KB) + red[8192] (32KB) = 98304 B.
__global__ __launch_bounds__(512, 1) void k_encoder(const float* __restrict__ W,
                                                    const float* __restrict__ bias,
                                                    const int* __restrict__ enc_len) {
    extern __shared__ float dsm[];
    float* xs  = dsm;
    float* red = dsm + 16384;
    const int j  = blockIdx.x;
    const int tt = threadIdx.x;
    const int cl = tt & 31, ks = tt >> 5;         // 16 k-slices of 64
    const int g  = cl >> 3, hl = cl & 7;
    const int col = g*1024 + j*8 + hl;
    const float* Wcol = W + (size_t)E_ * G4 + col;

    for (int t = 0; t < T_; t++) {
        const float* hbuf = g_hA + (t & 1)*BH;
        // stage h [1024 x 16] as xs[k*16+b]; 8 floats (one 32B sector) per unit
#pragma unroll
        for (int r = 0; r < 4; r++) {
            int i = tt + r*512;            // unit: k8 = i>>4 (0..127), b = i&15
            int b = i & 15, k8 = i >> 4;
            const float4* src = (const float4*)(hbuf + b*H_ + k8*8);
            float4 v0 = __ldcg(src);
            float4 v1 = __ldcg(src + 1);
            float* dst = xs + (k8*8)*16 + b;
            dst[0]  = v0.x; dst[16] = v0.y; dst[32] = v0.z; dst[48] = v0.w;
            dst[64] = v1.x; dst[80] = v1.y; dst[96] = v1.z; dst[112] = v1.w;
        }
        __syncthreads();

        ull acc2[8];
#pragma unroll
        for (int p = 0; p < 8; p++) acc2[p] = 0ull;
        const float* Wp = Wcol + (size_t)(ks*64) * G4;
        const ull* xp = (const ull*)xs + (ks*64)*8;
#pragma unroll
        for (int kb = 0; kb < 4; kb++) {
            float w[16];
#pragma unroll
            for (int u = 0; u < 16; u++) w[u] = Wp[(size_t)(kb*16+u) * G4];
#pragma unroll
            for (int u = 0; u < 16; u++) {
                ull wd = pk2(w[u]);
                const ull* x8 = xp + (kb*16+u)*8;
#pragma unroll
                for (int p = 0; p < 8; p++) ffma2(acc2[p], wd, x8[p]);
            }
        }
        __syncthreads();
#pragma unroll
        for (int p = 0; p < 8; p++) {
            float2 f = upk(acc2[p]);
            red[(2*p  )*512 + ks*32 + cl] = f.x;
            red[(2*p+1)*512 + ks*32 + cl] = f.y;
        }
        __syncthreads();

        if (tt < 128) {
            int hh = tt & 7, b = tt >> 3;
            int c0 = j*8 + hh;
            const float* zp = g_zpre_enc + (size_t)(b*T_ + t)*G4;
            float zi = zp[c0]        + bias[c0];
            float zj = zp[1024 + c0] + bias[1024 + c0];
            float zf = zp[2048 + c0] + bias[2048 + c0];
            float zo = zp[3072 + c0] + bias[3072 + c0];
#pragma unroll
            for (int s = 0; s < 16; s++) {
                const float* r = red + b*512 + s*32;
                zi += r[hh]; zj += r[8+hh]; zf += r[16+hh]; zo += r[24+hh];
            }
            int idx = b*H_ + c0;
            float cc = g_c[idx];
            float cn = cc * sigf(zf + 1.f) + sigf(zi)*tanh_fast(zj);
            float hn = tanh_fast(cn)*sigf(zo);
            bool valid = t < enc_len[b];
            if (valid) g_c[idx] = cn;
            float* hout = g_hA + ((t+1)&1)*BH;
            float hold = __ldcg(&hbuf[idx]);
            __stcg(&hout[idx], valid ? hn : hold);
            g_mem[(size_t)(b*T_ + t)*H_ + c0] = valid ? hn : 0.f;
        }
        grid_barrier(j, tt, (unsigned)(t + 1));
    }
}

// ================= persistent decoder =================
// 128 blocks x 512 threads. 5 barriers/step.
// dyn smem: xs[32768] floats (128KB) + red[8192] (32KB) = 163840 B.
__global__ __launch_bounds__(512, 1) void k_decoder(
    const float* __restrict__ Wd, const float* __restrict__ bias,
    const float* __restrict__ Wq, const float* __restrict__ v_att,
    const float* __restrict__ Wa,
    const int* __restrict__ enc_len, const int* __restrict__ dec_len) {
    extern __shared__ float dsm[];
    float* xs  = dsm;
    float* red = dsm + 32768;
    const int j  = blockIdx.x;
    const int tt = threadIdx.x;
    const int cl = tt & 31, ks = tt >> 5;          // phase A: 16 slices of 128
    const int g  = cl >> 3, hl = cl & 7;
    const int colA = g*1024 + j*8 + hl;
    const int cl8 = tt & 7, ks64 = tt >> 3;        // phases B/E: 64 slices
    const int colB = j*8 + cl8;
    const int bD = j >> 3;                         // phases C/D batch

    for (int t = 0; t < T_; t++) {
        const unsigned ep0 = 64u + 5u*(unsigned)t;
        const float* hbuf    = g_hA    + (t & 1)*BH;
        const float* attnbuf = g_attnA + (t & 1)*BH;
        float* h2buf         = g_hA    + ((t+1)&1)*BH;
        float* attn_nx       = g_attnA + ((t+1)&1)*BH;

        // ---- Phase A: z = [attn,h]@Wd + zpre + bias -> gates ----
        {
#pragma unroll
            for (int r = 0; r < 8; r++) {
                int i = tt + r*512;            // unit: k8 = i>>4 (0..255), b
                int b = i & 15, k8 = i >> 4;
                const float4* src = (k8 < 128)
                    ? (const float4*)(attnbuf + b*H_ + k8*8)
                    : (const float4*)(hbuf + b*H_ + (k8-128)*8);
                float4 v0 = __ldcg(src);
                float4 v1 = __ldcg(src + 1);
                float* dst = xs + (k8*8)*16 + b;
                dst[0]  = v0.x; dst[16] = v0.y; dst[32] = v0.z; dst[48] = v0.w;
                dst[64] = v1.x; dst[80] = v1.y; dst[96] = v1.z; dst[112] = v1.w;
            }
            __syncthreads();

            ull acc2[8];
#pragma unroll
            for (int p = 0; p < 8; p++) acc2[p] = 0ull;
            const float* Wp = Wd + (size_t)(E_ + ks*128) * G4 + colA;
            const ull* xp = (const ull*)xs + (ks*128)*8;
#pragma unroll
            for (int kb = 0; kb < 8; kb++) {
                float w[16];
#pragma unroll
                for (int u = 0; u < 16; u++) w[u] = Wp[(size_t)(kb*16+u) * G4];
#pragma unroll
                for (int u = 0; u < 16; u++) {
                    ull wd = pk2(w[u]);
                    const ull* x8 = xp + (kb*16+u)*8;
#pragma unroll
                    for (int p = 0; p < 8; p++) ffma2(acc2[p], wd, x8[p]);
                }
            }
            __syncthreads();
#pragma unroll
            for (int p = 0; p < 8; p++) {
                float2 f = upk(acc2[p]);
                red[(2*p  )*512 + ks*32 + cl] = f.x;
                red[(2*p+1)*512 + ks*32 + cl] = f.y;
            }
            __syncthreads();
            if (tt < 128) {
                int hh = tt & 7, b = tt >> 3;
                int c0 = j*8 + hh;
                const float* zp = g_zpre_dec + (size_t)(b*T_ + t)*G4;
                float zi = zp[c0]        + bias[c0];
                float zj = zp[1024 + c0] + bias[1024 + c0];
                float zf = zp[2048 + c0] + bias[2048 + c0];
                float zo = zp[3072 + c0] + bias[3072 + c0];
#pragma unroll
                for (int s = 0; s < 16; s++) {
                    const float* r = red + b*512 + s*32;
                    zi += r[hh]; zj += r[8+hh]; zf += r[16+hh]; zo += r[24+hh];
                }
                int idx = b*H_ + c0;
                float cc = g_c[idx];
                float cn = cc * sigf(zf + 1.f) + sigf(zi)*tanh_fast(zj);
                float hn = tanh_fast(cn)*sigf(zo);
                g_c[idx] = cn;
                __stcg(&h2buf[idx], hn);
            }
        }
        grid_barrier(j, tt, ep0 + 1);

        // ---- Phase B: query = h2 @ Wq ----
        {
#pragma unroll
            for (int r = 0; r < 4; r++) {
                int i = tt + r*512;
                int b = i & 15, k8 = i >> 4;   // k8 0..127
                const float4* src = (const float4*)(h2buf + b*H_ + k8*8);
                float4 v0 = __ldcg(src);
                float4 v1 = __ldcg(src + 1);
                float* dst = xs + (k8*8)*16 + b;
                dst[0]  = v0.x; dst[16] = v0.y; dst[32] = v0.z; dst[48] = v0.w;
                dst[64] = v1.x; dst[80] = v1.y; dst[96] = v1.z; dst[112] = v1.w;
            }
            __syncthreads();

            ull acc2[8];
#pragma unroll
            for (int p = 0; p < 8; p++) acc2[p] = 0ull;
            const float* Wp = Wq + (size_t)(ks64*16) * H_ + colB;
            const ull* xp = (const ull*)xs + (ks64*16)*8;
            float w[16];
#pragma unroll
            for (int u = 0; u < 16; u++) w[u] = Wp[(size_t)u * H_];
#pragma unroll
            for (int u = 0; u < 16; u++) {
                ull wd = pk2(w[u]);
                const ull* x8 = xp + u*8;
#pragma unroll
                for (int p = 0; p < 8; p++) ffma2(acc2[p], wd, x8[p]);
            }
            __syncthreads();
#pragma unroll
            for (int p = 0; p < 8; p++) {
                float2 f = upk(acc2[p]);
                red[(2*p  )*512 + ks64*8 + cl8] = f.x;
                red[(2*p+1)*512 + ks64*8 + cl8] = f.y;
            }
            __syncthreads();
            if (tt < 128) {
                int clq = tt & 7, b = tt >> 3;
                float q = 0.f;
#pragma unroll
                for (int s = 0; s < 64; s++) q += red[b*512 + s*8 + clq];
                __stcg(&g_q[b*H_ + j*8 + clq], q);
            }
        }
        grid_barrier(j, tt, ep0 + 2);

        // ---- Phase C: scores[bD][t2] = v . tanh(keys + q) ----
        {
            if (tt < 256) {
                float4 v = __ldcg((const float4*)(g_q + bD*H_) + tt);
                *(float4*)(xs + tt*4) = v;
            }
            __syncthreads();
            int w    = tt >> 5;                 // 16 warps
            int p    = w >> 1;                  // 8 pairs
            int half = w & 1;
            int lane = tt & 31;
            int t2 = (j & 7)*8 + p;
            const float* kr = g_keys + (size_t)(bD*T_ + t2)*H_;
            float s = 0.f;
            int h0 = half*512 + lane;
#pragma unroll 4
            for (int h = h0; h < half*512 + 512; h += 32)
                s += tanh_fast(kr[h] + xs[h]) * v_att[h];
#pragma unroll
            for (int o = 16; o > 0; o >>= 1) s += __shfl_xor_sync(0xffffffffu, s, o);
            if (lane == 0) red[w] = s;
            __syncthreads();
            if (tt < 8) {
                float val = red[2*tt] + red[2*tt + 1];
                __stcg(&g_scores[bD*T_ + (j & 7)*8 + tt], val);
            }
        }
        grid_barrier(j, tt, ep0 + 3);

        // ---- Phase D: softmax + context ----
        {
            float* al = red;
            if (tt < 32) {
                int L = enc_len[bD];
                float s0 = (tt      < L) ? __ldcg(&g_scores[bD*T_ + tt])      : NEGV;
                float s1 = (tt + 32 < L) ? __ldcg(&g_scores[bD*T_ + tt + 32]) : NEGV;
                float m = fmaxf(s0, s1);
#pragma unroll
                for (int o = 16; o > 0; o >>= 1) m = fmaxf(m, __shfl_xor_sync(0xffffffffu, m, o));
                float e0 = __expf(s0 - m), e1 = __expf(s1 - m);
                float ss = e0 + e1;
#pragma unroll
                for (int o = 16; o > 0; o >>= 1) ss += __shfl_xor_sync(0xffffffffu, ss, o);
                float inv = 1.f / ss;
                al[tt] = e0 * inv; al[tt + 32] = e1 * inv;
            }
            __syncthreads();
            if (tt < 128) {
                int h = (j & 7)*128 + tt;
                const float* mb = g_mem + (size_t)bD*T_*H_ + h;
                float a = 0.f;
#pragma unroll
                for (int t2 = 0; t2 < T_; t2++) a += al[t2] * mb[(size_t)t2 * H_];
                __stcg(&g_ctx[bD*H_ + h], a);
            }
        }
        grid_barrier(j, tt, ep0 + 4);

        // ---- Phase E: attn2 = [h2, ctx] @ Wa + finish ----
        {
#pragma unroll
            for (int r = 0; r < 8; r++) {
                int i = tt + r*512;
                int b = i & 15, k8 = i >> 4;   // k8 0..255
                const float4* src = (k8 < 128)
                    ? (const float4*)(h2buf + b*H_ + k8*8)
                    : (const float4*)(g_ctx + b*H_ + (k8-128)*8);
                float4 v0 = __ldcg(src);
                float4 v1 = __ldcg(src + 1);
                float* dst = xs + (k8*8)*16 + b;
                dst[0]  = v0.x; dst[16] = v0.y; dst[32] = v0.z; dst[48] = v0.w;
                dst[64] = v1.x; dst[80] = v1.y; dst[96] = v1.z; dst[112] = v1.w;
            }
            __syncthreads();

            ull acc2[8];
#pragma unroll
            for (int p = 0; p < 8; p++) acc2[p] = 0ull;
            const float* Wp = Wa + (size_t)(ks64*32) * H_ + colB;
            const ull* xp = (const ull*)xs + (ks64*32)*8;
#pragma unroll
            for (int kb = 0; kb < 2; kb++) {
                float w[16];
#pragma unroll
                for (int u = 0; u < 16; u++) w[u] = Wp[(size_t)(kb*16+u) * H_];
#pragma unroll
                for (int u = 0; u < 16; u++) {
                    ull wd = pk2(w[u]);
                    const ull* x8 = xp + (kb*16+u)*8;
#pragma unroll
                    for (int p = 0; p < 8; p++) ffma2(acc2[p], wd, x8[p]);
                }
            }
            __syncthreads();
#pragma unroll
            for (int p = 0; p < 8; p++) {
                float2 f = upk(acc2[p]);
                red[(2*p  )*512 + ks64*8 + cl8] = f.x;
                red[(2*p+1)*512 + ks64*8 + cl8] = f.y;
            }
            __syncthreads();
            if (tt < 128) {
                int cla = tt & 7, b = tt >> 3;
                float a = 0.f;
#pragma unroll
                for (int s = 0; s < 64; s++) a += red[b*512 + s*8 + cla];
                int hh = j*8 + cla;
                __stcg(&attn_nx[b*H_ + hh], a);
                g_dec_out[(size_t)(b*T_ + t)*H_ + hh] = (t < dec_len[b]) ? a : 0.f;
            }
        }
        grid_barrier(j, tt, ep0 + 5);
    }
}

// ---------------- FFMA2 SGEMM (keys + preprojections) ----------------
__global__ __launch_bounds__(256, 2) void sgemm128(int mode,
                                                   const float* __restrict__ Bm,
                                                   int N, int K) {
    const float* A; float* C;
    if (mode == 0)      { A = g_mem;  C = g_keys; }
    else if (mode == 2) { A = g_qemb; C = g_zpre_enc; }
    else                { A = g_remb; C = g_zpre_dec; }

    __shared__ __align__(16) float As[2][8][264];
    __shared__ __align__(16) float Bs[2][8][128];
    const int tid = threadIdx.x;
    const int m0 = blockIdx.y * 128, n0 = blockIdx.x * 128;
    const int tx = tid & 15, ty = tid >> 4;
    const int la_r = tid >> 1, la_c = (tid & 1) * 4;
    const int lb_r = tid >> 5, lb_c = (tid & 31) * 4;

    ull acc2[8][4];
#pragma unroll
    for (int i = 0; i < 8; i++) {
#pragma unroll
        for (int jp = 0; jp < 4; jp++) acc2[i][jp] = 0ull;
    }

    {
        float4 a4 = *(const float4*)(A  + (size_t)(m0 + la_r) * K + la_c);
        float4 b4 = *(const float4*)(Bm + (size_t)lb_r * N + n0 + lb_c);
        *(float2*)&As[0][la_c+0][2*la_r] = make_float2(a4.x, a4.x);
        *(float2*)&As[0][la_c+1][2*la_r] = make_float2(a4.y, a4.y);
        *(float2*)&As[0][la_c+2][2*la_r] = make_float2(a4.z, a4.z);
        *(float2*)&As[0][la_c+3][2*la_r] = make_float2(a4.w, a4.w);
        *(float4*)&Bs[0][lb_r][lb_c] = b4;
    }
    __syncthreads();

    const int nk = K / 8;
    for (int kt = 0; kt < nk; kt++) {
        const int cur = kt & 1;
        float4 a4n, b4n;
        const bool nx = (kt + 1) < nk;
        if (nx) {
            int kb = (kt + 1) * 8;
            a4n = *(const float4*)(A  + (size_t)(m0 + la_r) * K + kb + la_c);
            b4n = *(const float4*)(Bm + (size_t)(kb + lb_r) * N + n0 + lb_c);
        }
#pragma unroll
        for (int k = 0; k < 8; k++) {
            const ull* ap = (const ull*)&As[cur][k][0];
            const ull* bp = (const ull*)&Bs[cur][k][0];
            ull av[8], bv[4];
#pragma unroll
            for (int i = 0; i < 4; i++) {
                av[i]   = ap[ty*4 + i];
                av[4+i] = ap[64 + ty*4 + i];
            }
            bv[0] = bp[tx*2];      bv[1] = bp[tx*2 + 1];
            bv[2] = bp[32 + tx*2]; bv[3] = bp[32 + tx*2 + 1];
#pragma unroll
            for (int i = 0; i < 8; i++) {
#pragma unroll
                for (int jp = 0; jp < 4; jp++) ffma2(acc2[i][jp], av[i], bv[jp]);
            }
        }
        if (nx) {
            const int nxt = cur ^ 1;
            *(float2*)&As[nxt][la_c+0][2*la_r] = make_float2(a4n.x, a4n.x);
            *(float2*)&As[nxt][la_c+1][2*la_r] = make_float2(a4n.y, a4n.y);
            *(float2*)&As[nxt][la_c+2][2*la_r] = make_float2(a4n.z, a4n.z);
            *(float2*)&As[nxt][la_c+3][2*la_r] = make_float2(a4n.w, a4n.w);
            *(float4*)&Bs[nxt][lb_r][lb_c] = b4n;
            __syncthreads();
        }
    }

#pragma unroll
    for (int i = 0; i < 8; i++) {
        int r = m0 + ((i < 4) ? (ty*4 + i) : (64 + ty*4 + (i - 4)));
        float2 p0 = upk(acc2[i][0]), p1 = upk(acc2[i][1]);
        float2 p2 = upk(acc2[i][2]), p3 = upk(acc2[i][3]);
        float4 v0 = make_float4(p0.x, p0.y, p1.x, p1.y);
        float4 v1 = make_float4(p2.x, p2.y, p3.x, p3.y);
        *(float4*)(C + (size_t)r * N + n0 + tx*4)      = v0;
        *(float4*)(C + (size_t)r * N + n0 + 64 + tx*4) = v1;
    }
}

// ================= logits on tensor cores (bf16 hi/lo split) ==============
__global__ void k_splitA() {
    int i = blockIdx.x * 512 + threadIdx.x;
    float x = g_dec_out[i];
    __nv_bfloat16 h = __float2bfloat16(x);
    g_Ahi[i] = h;
    g_Alo[i] = __float2bfloat16(x - __bfloat162float(h));
}

__global__ __launch_bounds__(512, 1) void k_logits(const float* __restrict__ Wk,
                                                   float* __restrict__ C) {
    extern __shared__ char smbuf[];
    __nv_bfloat16* sAhi = (__nv_bfloat16*)(smbuf);
    __nv_bfloat16* sAlo = (__nv_bfloat16*)(smbuf + 24576);
    __nv_bfloat16* sWhi = (__nv_bfloat16*)(smbuf + 49152);
    __nv_bfloat16* sWlo = (__nv_bfloat16*)(smbuf + 57856);
    const int tid  = threadIdx.x;
    const int lane = tid & 31;
    const int warp = tid >> 5;
    const int wm = warp & 3;
    const int wn = warp >> 2;
    const int n0 = blockIdx.x * 128;
    const int m0 = blockIdx.y * 256;
    const int ar = tid >> 1;
    const int ac = (tid & 1) * 8;
    const int wr = tid >> 5;
    const int wc = (tid & 31) * 4;

    const uint32_t uAhi = (uint32_t)__cvta_generic_to_shared(sAhi);
    const uint32_t uAlo = (uint32_t)__cvta_generic_to_shared(sAlo);
    const uint32_t uWhi = (uint32_t)__cvta_generic_to_shared(sWhi);
    const uint32_t uWlo = (uint32_t)__cvta_generic_to_shared(sWlo);

    const int aRow  = lane & 15;
    const int aColB = (lane >> 4) * 16;

    float acc[4][4][4];
#pragma unroll
    for (int mt = 0; mt < 4; mt++) {
#pragma unroll
        for (int nt = 0; nt < 4; nt++) {
#pragma unroll
            for (int q = 0; q < 4; q++) acc[mt][nt][q] = 0.0f;
        }
    }

    {
        uint4 va = *(const uint4*)(g_Ahi + (size_t)(m0 + ar) * H_ + ac);
        uint4 vl = *(const uint4*)(g_Alo + (size_t)(m0 + ar) * H_ + ac);
        *(uint4*)(sAhi + ar * 24 + ac) = va;
        *(uint4*)(sAlo + ar * 24 + ac) = vl;
        float4 w4 = *(const float4*)(Wk + (size_t)wr * V_ + n0 + wc);
        __nv_bfloat16 h0 = __float2bfloat16(w4.x);
        __nv_bfloat16 h1 = __float2bfloat16(w4.y);
        __nv_bfloat16 h2 = __float2bfloat16(w4.z);
        __nv_bfloat16 h3 = __float2bfloat16(w4.w);
        __nv_bfloat16 l0 = __float2bfloat16(w4.x - __bfloat162float(h0));
        __nv_bfloat16 l1 = __float2bfloat16(w4.y - __bfloat162float(h1));
        __nv_bfloat16 l2 = __float2bfloat16(w4.z - __bfloat162float(h2));
        __nv_bfloat16 l3 = __float2bfloat16(w4.w - __bfloat162float(h3));
        *(uint32_t*)(sWhi + wr * 136 + wc)     = pack_bf16x2(h0, h1);
        *(uint32_t*)(sWhi + wr * 136 + wc + 2) = pack_bf16x2(h2, h3);
        *(uint32_t*)(sWlo + wr * 136 + wc)     = pack_bf16x2(l0, l1);
        *(uint32_t*)(sWlo + wr * 136 + wc + 2) = pack_bf16x2(l2, l3);
    }
    __syncthreads();

    for (int kt = 0; kt < 64; kt++) {
        const int buf = kt & 1;
        const bool has = (kt < 63);
        uint4 na, nl;
        float4 nw;
        if (has) {
            int kn = (kt + 1) * 16;
            na = *(const uint4*)(g_Ahi + (size_t)(m0 + ar) * H_ + kn + ac);
            nl = *(const uint4*)(g_Alo + (size_t)(m0 + ar) * H_ + kn + ac);
            nw = *(const float4*)(Wk + (size_t)(kn + wr) * V_ + n0 + wc);
        }

        uint32_t bhi[2][4];
        uint32_t blo[2][4];
#pragma unroll
        for (int ch = 0; ch < 2; ch++) {
            uint32_t off = (uint32_t)(((buf * 16 + aRow) * 136 + wn * 32 + ch * 16) * 2 + aColB);
            ldm_x4t(bhi[ch], uWhi + off);
            ldm_x4t(blo[ch], uWlo + off);
        }

#pragma unroll
        for (int mt = 0; mt < 4; mt++) {
            uint32_t ah[4];
            uint32_t al[4];
            uint32_t off = (uint32_t)(((buf * 256 + wm * 64 + mt * 16 + aRow) * 24) * 2 + aColB);
            ldm_x4(ah, uAhi + off);
            ldm_x4(al, uAlo + off);
#pragma unroll
            for (int nt = 0; nt < 4; nt++) {
                uint32_t b0 = bhi[nt >> 1][(nt & 1) * 2];
                uint32_t b1 = bhi[nt >> 1][(nt & 1) * 2 + 1];
                uint32_t c0 = blo[nt >> 1][(nt & 1) * 2];
                uint32_t c1 = blo[nt >> 1][(nt & 1) * 2 + 1];
                mma_bf16(acc[mt][nt], ah, b0, b1);
                mma_bf16(acc[mt][nt], al, b0, b1);
                mma_bf16(acc[mt][nt], ah, c0, c1);
            }
        }

        if (has) {
            const int nbuf = buf ^ 1;
            *(uint4*)(sAhi + (nbuf * 256 + ar) * 24 + ac) = na;
            *(uint4*)(sAlo + (nbuf * 256 + ar) * 24 + ac) = nl;
            __nv_bfloat16 h0 = __float2bfloat16(nw.x);
            __nv_bfloat16 h1 = __float2bfloat16(nw.y);
            __nv_bfloat16 h2 = __float2bfloat16(nw.z);
            __nv_bfloat16 h3 = __float2bfloat16(nw.w);
            __nv_bfloat16 l0 = __float2bfloat16(nw.x - __bfloat162float(h0));
            __nv_bfloat16 l1 = __float2bfloat16(nw.y - __bfloat162float(h1));
            __nv_bfloat16 l2 = __float2bfloat16(nw.z - __bfloat162float(h2));
            __nv_bfloat16 l3 = __float2bfloat16(nw.w - __bfloat162float(h3));
            *(uint32_t*)(sWhi + (nbuf * 16 + wr) * 136 + wc)     = pack_bf16x2(h0, h1);
            *(uint32_t*)(sWhi + (nbuf * 16 + wr) * 136 + wc + 2) = pack_bf16x2(h2, h3);
            *(uint32_t*)(sWlo + (nbuf * 16 + wr) * 136 + wc)     = pack_bf16x2(l0, l1);
            *(uint32_t*)(sWlo + (nbuf * 16 + wr) * 136 + wc + 2) = pack_bf16x2(l2, l3);
        }
        __syncthreads();
    }

#pragma unroll
    for (int mt = 0; mt < 4; mt++) {
        int row = m0 + wm * 64 + mt * 16 + (lane >> 2);
#pragma unroll
        for (int nt = 0; nt < 4; nt++) {
            int col = n0 + wn * 32 + nt * 8 + (lane & 3) * 2;
            *(float2*)(C + (size_t)row * V_ + col) =
                make_float2(acc[mt][nt][0], acc[mt][nt][1]);
            *(float2*)(C + (size_t)(row + 8) * V_ + col) =
                make_float2(acc[mt][nt][2], acc[mt][nt][3]);
        }
    }
}

// ------------------------------ launcher ----------------------------------
extern "C" void kernel_launch(void* const* d_in, const int* in_sizes, int n_in,
                              void* d_out, int out_size) {
    const int*   enc_in  = (const int*)  d_in[0];
    const int*   dec_in  = (const int*)  d_in[1];
    const int*   enc_len = (const int*)  d_in[2];
    const int*   dec_len = (const int*)  d_in[3];
    const float* emb     = (const float*)d_in[4];
    const float* enc_k   = (const float*)d_in[5];
    const float* enc_b   = (const float*)d_in[6];
    const float* dec_k   = (const float*)d_in[7];
    const float* dec_b   = (const float*)d_in[8];
    const float* Wm      = (const float*)d_in[9];
    const float* Wq      = (const float*)d_in[10];
    const float* v_att   = (const float*)d_in[11];
    const float* attn_k  = (const float*)d_in[12];
    const float* out_k   = (const float*)d_in[13];
    float* out = (float*)d_out;

    cudaFuncSetAttribute(k_logits,  cudaFuncAttributeMaxDynamicSharedMemorySize, 66560);
    cudaFuncSetAttribute(k_encoder, cudaFuncAttributeMaxDynamicSharedMemorySize, 98304);
    cudaFuncSetAttribute(k_decoder, cudaFuncAttributeMaxDynamicSharedMemorySize, 163840);

    // embeddings + zero state + barrier reset
    k_init<<<2368, 256>>>(enc_in, dec_in, emb);

    // precompute input projections for all timesteps
    sgemm128<<<dim3(32, 8), 256>>>(2, enc_k, G4, E_);
    sgemm128<<<dim3(32, 8), 256>>>(3, dec_k, G4, E_);

    // persistent encoder (64 steps, 1 barrier each)
    k_encoder<<<NBLK, 512, 98304>>>(enc_k, enc_b, enc_len);

    // keys = memory @ Wm
    sgemm128<<<dim3(8, 8), 256>>>(0, Wm, H_, H_);

    // persistent decoder (64 steps, 5 barriers each)
    k_decoder<<<NBLK, 512, 163840>>>(dec_k, dec_b, Wq, v_att, attn_k,
                                     enc_len, dec_len);

    // logits on tensor cores
    k_splitA<<<2048, 512>>>();
    k_logits<<<dim3(250, 4), 512, 66560>>>(out_k, out);
}